// round 2
// baseline (speedup 1.0000x reference)
#include <cuda_runtime.h>
#include <math.h>

#define BATCH 2
#define SEQ   2048
#define DIM   1024
#define HEADS 16
#define HDIM  64
#define NTOK  (BATCH*SEQ)          // 4096
#define QKV_N (3*DIM)              // 3072

// Scratch (device globals — no allocation allowed)
__device__ float g_q[BATCH*HEADS*SEQ*HDIM];     // (B,H,S,HD)
__device__ float g_k[BATCH*HEADS*SEQ*HDIM];
__device__ float g_v[BATCH*HEADS*SEQ*HDIM];
__device__ float g_attn[NTOK*DIM];              // (B,S,D)
__device__ float g_cos[SEQ*32];
__device__ float g_sin[SEQ*32];

// ---------------------------------------------------------------------------
// RoPE table: theta(s, j) = s * 10000^(-j/32), fp64 for accuracy
// ---------------------------------------------------------------------------
__global__ void rope_table_kernel() {
    int idx = blockIdx.x * blockDim.x + threadIdx.x;
    if (idx >= SEQ * 32) return;
    int s = idx >> 5;
    int j = idx & 31;
    double theta = (double)s * pow(10000.0, -(double)j / 32.0);
    double sc, cc;
    sincos(theta, &sc, &cc);
    g_cos[idx] = (float)cc;
    g_sin[idx] = (float)sc;
}

// ---------------------------------------------------------------------------
// QKV GEMM (4096 x 3072 x 1024) + bias + RoPE epilogue, permuted writes.
// 128x128 block tile, BK=8, 256 threads, 8x8 micro-tile.
// Micro-tile columns per thread: within one head, cols {t8*4..+3} and
// {t8*4+32..+35} -> the rotate-half pair (d, d+32) is in-thread.
// ---------------------------------------------------------------------------
__global__ __launch_bounds__(256) void qkv_rope_kernel(
    const float* __restrict__ X,      // (4096, 1024)
    const float* __restrict__ W,      // (1024, 3072)
    const float* __restrict__ bias)   // (3072,)
{
    __shared__ float As[8][128];
    __shared__ float Bs[8][128];

    const int tid = threadIdx.x;
    const int tx = tid & 15;          // 0..15
    const int ty = tid >> 4;          // 0..15
    const int h2 = tx >> 3;           // which head within 128-col tile
    const int t8 = tx & 7;            // 0..7 -> d base = t8*4

    const int row0 = blockIdx.y * 128;
    const int col0 = blockIdx.x * 128;

    // global-load indexing
    const int arow = tid >> 1;            // 0..127
    const int acol = (tid & 1) * 4;       // 0 or 4
    const int brow = tid >> 5;            // 0..7
    const int bcol = (tid & 31) * 4;      // 0..124

    const float* Aptr = X + (size_t)(row0 + arow) * DIM + acol;
    const float* Bptr = W + (size_t)brow * QKV_N + col0 + bcol;

    float acc[8][8];
#pragma unroll
    for (int i = 0; i < 8; i++)
#pragma unroll
        for (int j = 0; j < 8; j++) acc[i][j] = 0.0f;

    for (int k0 = 0; k0 < DIM; k0 += 8) {
        float4 av = *(const float4*)(Aptr + k0);
        float4 bv = *(const float4*)(Bptr + (size_t)k0 * QKV_N);
        __syncthreads();
        As[acol + 0][arow] = av.x;
        As[acol + 1][arow] = av.y;
        As[acol + 2][arow] = av.z;
        As[acol + 3][arow] = av.w;
        *(float4*)&Bs[brow][bcol] = bv;
        __syncthreads();

#pragma unroll
        for (int kk = 0; kk < 8; kk++) {
            float a[8], b[8];
            *(float4*)&a[0] = *(const float4*)&As[kk][ty * 8];
            *(float4*)&a[4] = *(const float4*)&As[kk][ty * 8 + 4];
            *(float4*)&b[0] = *(const float4*)&Bs[kk][h2 * 64 + t8 * 4];
            *(float4*)&b[4] = *(const float4*)&Bs[kk][h2 * 64 + t8 * 4 + 32];
#pragma unroll
            for (int i = 0; i < 8; i++)
#pragma unroll
                for (int j = 0; j < 8; j++)
                    acc[i][j] = fmaf(a[i], b[j], acc[i][j]);
        }
    }

    // Epilogue: bias + RoPE (for q,k) + permuted store
    const int c = col0 / DIM;               // 0=q, 1=k, 2=v (tile never straddles)
    float* dst = (c == 0) ? g_q : (c == 1) ? g_k : g_v;

#pragma unroll
    for (int i = 0; i < 8; i++) {
        const int t = row0 + ty * 8 + i;        // token index
        const int bb = t >> 11;                 // batch
        const int s = t & (SEQ - 1);            // position
#pragma unroll
        for (int j = 0; j < 4; j++) {
            const int colL = h2 * 64 + t8 * 4 + j;   // local col, d < 32 part
            const int n = col0 + colL;
            const int d = t8 * 4 + j;                // 0..31
            const int h = (n >> 6) & (HEADS - 1);
            float x1 = acc[i][j]     + bias[n];
            float x2 = acc[i][j + 4] + bias[n + 32];
            float o1, o2;
            if (c < 2) {
                const float cs = g_cos[s * 32 + d];
                const float sn = g_sin[s * 32 + d];
                o1 = x1 * cs - x2 * sn;
                o2 = x2 * cs + x1 * sn;
            } else {
                o1 = x1; o2 = x2;
            }
            const size_t base = (((size_t)bb * HEADS + h) * SEQ + s) * HDIM;
            dst[base + d]      = o1;
            dst[base + d + 32] = o2;
        }
    }
}

// ---------------------------------------------------------------------------
// Flash attention: grid (B*H, S/128), 128 threads, 1 thread = 1 query row.
// KV tiles of 32 keys staged in smem; online softmax; causal.
// ---------------------------------------------------------------------------
__global__ __launch_bounds__(128) void attn_kernel() {
    const int bh = blockIdx.x;                  // 0..31
    const int qt = blockIdx.y;                  // 0..15
    const int tid = threadIdx.x;

    const float* Q = g_q + (size_t)bh * SEQ * HDIM;
    const float* K = g_k + (size_t)bh * SEQ * HDIM;
    const float* V = g_v + (size_t)bh * SEQ * HDIM;

    const int qrow = qt * 128 + tid;

    float q[64];
#pragma unroll
    for (int d4 = 0; d4 < 16; d4++) {
        float4 v4 = *(const float4*)(Q + (size_t)qrow * HDIM + d4 * 4);
        q[d4 * 4 + 0] = v4.x; q[d4 * 4 + 1] = v4.y;
        q[d4 * 4 + 2] = v4.z; q[d4 * 4 + 3] = v4.w;
    }

    float o[64];
#pragma unroll
    for (int d = 0; d < 64; d++) o[d] = 0.0f;
    float m = -1e30f;
    float l = 0.0f;

    __shared__ float Ks[32][64];
    __shared__ float Vs[32][64];

    const float scale = 0.125f;                 // 1/sqrt(64)
    const int kmax = qt * 128 + 128;            // exclusive

    for (int k0 = 0; k0 < kmax; k0 += 32) {
        __syncthreads();
        // cooperative load: 32*64 floats = 512 float4 per tile, 128 threads
        const float4* Kg = (const float4*)(K + (size_t)k0 * HDIM);
        const float4* Vg = (const float4*)(V + (size_t)k0 * HDIM);
        float4* Kss = (float4*)&Ks[0][0];
        float4* Vss = (float4*)&Vs[0][0];
#pragma unroll
        for (int it = 0; it < 4; it++) {
            int i = tid + it * 128;
            Kss[i] = Kg[i];
            Vss[i] = Vg[i];
        }
        __syncthreads();

        if (k0 <= qrow) {
            float p[32];
            float mloc = m;
#pragma unroll 4
            for (int j = 0; j < 32; j++) {
                float dot = 0.0f;
#pragma unroll
                for (int d4 = 0; d4 < 16; d4++) {
                    float4 kv = *(const float4*)&Ks[j][d4 * 4];
                    dot = fmaf(q[d4 * 4 + 0], kv.x, dot);
                    dot = fmaf(q[d4 * 4 + 1], kv.y, dot);
                    dot = fmaf(q[d4 * 4 + 2], kv.z, dot);
                    dot = fmaf(q[d4 * 4 + 3], kv.w, dot);
                }
                dot *= scale;
                if (k0 + j > qrow) dot = -1e30f;
                p[j] = dot;
                mloc = fmaxf(mloc, dot);
            }
            const float corr = expf(m - mloc);
            float sum = 0.0f;
#pragma unroll 4
            for (int j = 0; j < 32; j++) {
                p[j] = expf(p[j] - mloc);
                sum += p[j];
            }
            l = l * corr + sum;
#pragma unroll
            for (int d = 0; d < 64; d++) o[d] *= corr;
#pragma unroll 2
            for (int j = 0; j < 32; j++) {
                const float pj = p[j];
#pragma unroll
                for (int d4 = 0; d4 < 16; d4++) {
                    float4 vv = *(const float4*)&Vs[j][d4 * 4];
                    o[d4 * 4 + 0] = fmaf(pj, vv.x, o[d4 * 4 + 0]);
                    o[d4 * 4 + 1] = fmaf(pj, vv.y, o[d4 * 4 + 1]);
                    o[d4 * 4 + 2] = fmaf(pj, vv.z, o[d4 * 4 + 2]);
                    o[d4 * 4 + 3] = fmaf(pj, vv.w, o[d4 * 4 + 3]);
                }
            }
            m = mloc;
        }
    }

    const float invl = 1.0f / l;
    const int bb = bh >> 4;
    const int h = bh & (HEADS - 1);
    float* dst = g_attn + ((size_t)bb * SEQ + qrow) * DIM + h * HDIM;
#pragma unroll
    for (int d4 = 0; d4 < 16; d4++) {
        float4 v4;
        v4.x = o[d4 * 4 + 0] * invl;
        v4.y = o[d4 * 4 + 1] * invl;
        v4.z = o[d4 * 4 + 2] * invl;
        v4.w = o[d4 * 4 + 3] * invl;
        *(float4*)(dst + d4 * 4) = v4;
    }
}

// ---------------------------------------------------------------------------
// Output projection GEMM (4096 x 1024 x 1024) + bias -> d_out
// Reads g_attn DIRECTLY as a device symbol (never passed from host!).
// ---------------------------------------------------------------------------
__global__ __launch_bounds__(256) void out_gemm_kernel(
    const float* __restrict__ W,      // (1024, 1024)
    const float* __restrict__ bias,   // (1024,)
    float* __restrict__ out)          // (4096, 1024)
{
    __shared__ float As[8][128];
    __shared__ float Bs[8][128];

    const float* A = g_attn;

    const int tid = threadIdx.x;
    const int tx = tid & 15;
    const int ty = tid >> 4;

    const int row0 = blockIdx.y * 128;
    const int col0 = blockIdx.x * 128;

    const int arow = tid >> 1;
    const int acol = (tid & 1) * 4;
    const int brow = tid >> 5;
    const int bcol = (tid & 31) * 4;

    const float* Aptr = A + (size_t)(row0 + arow) * DIM + acol;
    const float* Bptr = W + (size_t)brow * DIM + col0 + bcol;

    float acc[8][8];
#pragma unroll
    for (int i = 0; i < 8; i++)
#pragma unroll
        for (int j = 0; j < 8; j++) acc[i][j] = 0.0f;

    for (int k0 = 0; k0 < DIM; k0 += 8) {
        float4 av = *(const float4*)(Aptr + k0);
        float4 bv = *(const float4*)(Bptr + (size_t)k0 * DIM);
        __syncthreads();
        As[acol + 0][arow] = av.x;
        As[acol + 1][arow] = av.y;
        As[acol + 2][arow] = av.z;
        As[acol + 3][arow] = av.w;
        *(float4*)&Bs[brow][bcol] = bv;
        __syncthreads();

#pragma unroll
        for (int kk = 0; kk < 8; kk++) {
            float a[8], b[8];
            *(float4*)&a[0] = *(const float4*)&As[kk][ty * 8];
            *(float4*)&a[4] = *(const float4*)&As[kk][ty * 8 + 4];
            *(float4*)&b[0] = *(const float4*)&Bs[kk][tx * 8];
            *(float4*)&b[4] = *(const float4*)&Bs[kk][tx * 8 + 4];
#pragma unroll
            for (int i = 0; i < 8; i++)
#pragma unroll
                for (int j = 0; j < 8; j++)
                    acc[i][j] = fmaf(a[i], b[j], acc[i][j]);
        }
    }

#pragma unroll
    for (int i = 0; i < 8; i++) {
        const int r = row0 + ty * 8 + i;
#pragma unroll
        for (int j = 0; j < 8; j++) {
            const int cidx = col0 + tx * 8 + j;
            out[(size_t)r * DIM + cidx] = acc[i][j] + bias[cidx];
        }
    }
}

// ---------------------------------------------------------------------------
extern "C" void kernel_launch(void* const* d_in, const int* in_sizes, int n_in,
                              void* d_out, int out_size) {
    // Bind inputs by element count (robust to metadata ordering):
    // query=4194304, W_qkv=3145728, b_qkv=3072, W_out=1048576, b_out=1024
    const float* query = 0;
    const float* W_qkv = 0;
    const float* b_qkv = 0;
    const float* W_out = 0;
    const float* b_out = 0;
    for (int i = 0; i < n_in; i++) {
        switch (in_sizes[i]) {
            case 4194304: query = (const float*)d_in[i]; break;
            case 3145728: W_qkv = (const float*)d_in[i]; break;
            case 3072:    b_qkv = (const float*)d_in[i]; break;
            case 1048576: W_out = (const float*)d_in[i]; break;
            case 1024:    b_out = (const float*)d_in[i]; break;
        }
    }
    float* out = (float*)d_out;

    rope_table_kernel<<<(SEQ * 32 + 255) / 256, 256>>>();

    {
        dim3 grid(QKV_N / 128, NTOK / 128);       // (24, 32)
        qkv_rope_kernel<<<grid, 256>>>(query, W_qkv, b_qkv);
    }
    {
        dim3 grid(BATCH * HEADS, SEQ / 128);      // (32, 16)
        attn_kernel<<<grid, 128>>>();
    }
    {
        dim3 grid(DIM / 128, NTOK / 128);         // (8, 32)
        out_gemm_kernel<<<grid, 256>>>(W_out, b_out, out);
    }
}

// round 3
// speedup vs baseline: 1.0248x; 1.0248x over previous
#include <cuda_runtime.h>
#include <math.h>

#define BATCH 2
#define SEQ   2048
#define DIM   1024
#define HEADS 16
#define HDIM  64
#define NTOK  (BATCH*SEQ)          // 4096
#define QKV_N (3*DIM)              // 3072

typedef unsigned long long u64;

// ---- packed f32x2 helpers (Blackwell FFMA2 path) --------------------------
__device__ __forceinline__ u64 pack2(float lo, float hi) {
    u64 r; asm("mov.b64 %0, {%1, %2};" : "=l"(r) : "f"(lo), "f"(hi)); return r;
}
__device__ __forceinline__ float2 unpack2(u64 v) {
    float2 f; asm("mov.b64 {%0, %1}, %2;" : "=f"(f.x), "=f"(f.y) : "l"(v)); return f;
}
__device__ __forceinline__ void fma2(u64 &d, u64 a, u64 b) {
    asm("fma.rn.f32x2 %0, %1, %2, %0;" : "+l"(d) : "l"(a), "l"(b));
}
__device__ __forceinline__ u64 mul2(u64 a, u64 b) {
    u64 r; asm("mul.rn.f32x2 %0, %1, %2;" : "=l"(r) : "l"(a), "l"(b)); return r;
}
__device__ __forceinline__ u64 add2(u64 a, u64 b) {
    u64 r; asm("add.rn.f32x2 %0, %1, %2;" : "=l"(r) : "l"(a), "l"(b)); return r;
}

// Scratch (device globals — no allocation allowed)
__device__ float g_q[BATCH*HEADS*SEQ*HDIM];     // (B,H,S,HD)
__device__ float g_k[BATCH*HEADS*SEQ*HDIM];
__device__ float g_v[BATCH*HEADS*SEQ*HDIM];
__device__ float g_attn[NTOK*DIM];              // (B,S,D)
__device__ float g_cos[SEQ*32];
__device__ float g_sin[SEQ*32];

// ---------------------------------------------------------------------------
// RoPE table: theta(s, j) = s * 10000^(-j/32), fp64 for accuracy
// ---------------------------------------------------------------------------
__global__ void rope_table_kernel() {
    int idx = blockIdx.x * blockDim.x + threadIdx.x;
    if (idx >= SEQ * 32) return;
    int s = idx >> 5;
    int j = idx & 31;
    double theta = (double)s * pow(10000.0, -(double)j / 32.0);
    double sc, cc;
    sincos(theta, &sc, &cc);
    g_cos[idx] = (float)cc;
    g_sin[idx] = (float)sc;
}

// ---------------------------------------------------------------------------
// QKV GEMM (4096 x 3072 x 1024) + bias + RoPE epilogue, permuted writes.
// 128x128 tile, BK=8, 256 threads, 8x8 micro-tile, packed f32x2 inner loop.
// As2 holds each A value DUPLICATED so an LDS.128 yields two broadcast pairs.
// ---------------------------------------------------------------------------
__global__ __launch_bounds__(256) void qkv_rope_kernel(
    const float* __restrict__ X,      // (4096, 1024)
    const float* __restrict__ W,      // (1024, 3072)
    const float* __restrict__ bias)   // (3072,)
{
    __shared__ __align__(16) float As2[8][256];   // duplicated A
    __shared__ __align__(16) float Bs[8][128];

    const int tid = threadIdx.x;
    const int tx = tid & 15;          // 0..15
    const int ty = tid >> 4;          // 0..15
    const int h2 = tx >> 3;           // which head within 128-col tile
    const int t8 = tx & 7;            // 0..7 -> d base = t8*4

    const int row0 = blockIdx.y * 128;
    const int col0 = blockIdx.x * 128;

    const int arow = tid >> 1;            // 0..127
    const int acol = (tid & 1) * 4;       // 0 or 4
    const int brow = tid >> 5;            // 0..7
    const int bcol = (tid & 31) * 4;      // 0..124

    const float* Aptr = X + (size_t)(row0 + arow) * DIM + acol;
    const float* Bptr = W + (size_t)brow * QKV_N + col0 + bcol;

    u64 acc_p[8][4];
#pragma unroll
    for (int i = 0; i < 8; i++)
#pragma unroll
        for (int j = 0; j < 4; j++) acc_p[i][j] = 0ull;

    float4 av = *(const float4*)(Aptr);
    float4 bv = *(const float4*)(Bptr);

    for (int k0 = 0; k0 < DIM; k0 += 8) {
        __syncthreads();
        *(u64*)&As2[acol + 0][2 * arow] = pack2(av.x, av.x);
        *(u64*)&As2[acol + 1][2 * arow] = pack2(av.y, av.y);
        *(u64*)&As2[acol + 2][2 * arow] = pack2(av.z, av.z);
        *(u64*)&As2[acol + 3][2 * arow] = pack2(av.w, av.w);
        *(float4*)&Bs[brow][bcol] = bv;
        __syncthreads();

        if (k0 + 8 < DIM) {
            av = *(const float4*)(Aptr + k0 + 8);
            bv = *(const float4*)(Bptr + (size_t)(k0 + 8) * QKV_N);
        }

#pragma unroll
        for (int kk = 0; kk < 8; kk++) {
            ulonglong2 a01 = *(const ulonglong2*)&As2[kk][2 * (ty * 8) + 0];
            ulonglong2 a23 = *(const ulonglong2*)&As2[kk][2 * (ty * 8) + 4];
            ulonglong2 a45 = *(const ulonglong2*)&As2[kk][2 * (ty * 8) + 8];
            ulonglong2 a67 = *(const ulonglong2*)&As2[kk][2 * (ty * 8) + 12];
            ulonglong2 bL = *(const ulonglong2*)&Bs[kk][h2 * 64 + t8 * 4];
            ulonglong2 bH = *(const ulonglong2*)&Bs[kk][h2 * 64 + t8 * 4 + 32];
            u64 ap[8] = {a01.x, a01.y, a23.x, a23.y, a45.x, a45.y, a67.x, a67.y};
            u64 bp[4] = {bL.x, bL.y, bH.x, bH.y};
#pragma unroll
            for (int i = 0; i < 8; i++)
#pragma unroll
                for (int j = 0; j < 4; j++)
                    fma2(acc_p[i][j], ap[i], bp[j]);
        }
    }

    // Epilogue: bias + RoPE (for q,k) + permuted store
    const int c = col0 / DIM;               // 0=q, 1=k, 2=v (tile never straddles)
    float* dst = (c == 0) ? g_q : (c == 1) ? g_k : g_v;

    const int ncol = col0 + h2 * 64 + t8 * 4;     // first (low) column
    float bi_lo[4], bi_hi[4];
#pragma unroll
    for (int j = 0; j < 4; j++) {
        bi_lo[j] = bias[ncol + j];
        bi_hi[j] = bias[ncol + j + 32];
    }
    const int d0 = t8 * 4;
    const int h = (ncol >> 6) & (HEADS - 1);

#pragma unroll
    for (int i = 0; i < 8; i++) {
        const int t = row0 + ty * 8 + i;        // token index
        const int bb = t >> 11;                 // batch
        const int s = t & (SEQ - 1);            // position
        float ac[8];
        float2 f;
        f = unpack2(acc_p[i][0]); ac[0] = f.x; ac[1] = f.y;
        f = unpack2(acc_p[i][1]); ac[2] = f.x; ac[3] = f.y;
        f = unpack2(acc_p[i][2]); ac[4] = f.x; ac[5] = f.y;
        f = unpack2(acc_p[i][3]); ac[6] = f.x; ac[7] = f.y;
        const size_t base = (((size_t)bb * HEADS + h) * SEQ + s) * HDIM;
#pragma unroll
        for (int j = 0; j < 4; j++) {
            const int d = d0 + j;                    // 0..31
            float x1 = ac[j]     + bi_lo[j];
            float x2 = ac[j + 4] + bi_hi[j];
            float o1, o2;
            if (c < 2) {
                const float cs = g_cos[s * 32 + d];
                const float sn = g_sin[s * 32 + d];
                o1 = x1 * cs - x2 * sn;
                o2 = x2 * cs + x1 * sn;
            } else {
                o1 = x1; o2 = x2;
            }
            dst[base + d]      = o1;
            dst[base + d + 32] = o2;
        }
    }
}

// ---------------------------------------------------------------------------
// Flash attention: grid (B*H, S/128), 128 threads, 1 thread = 1 query row.
// KV tiles of 32 keys in smem; packed f32x2 QK and PV; online softmax; causal.
// ---------------------------------------------------------------------------
__global__ __launch_bounds__(128) void attn_kernel() {
    const int bh = blockIdx.x;                  // 0..31
    const int qt = blockIdx.y;                  // 0..15
    const int tid = threadIdx.x;

    const float* Q = g_q + (size_t)bh * SEQ * HDIM;
    const float* K = g_k + (size_t)bh * SEQ * HDIM;
    const float* V = g_v + (size_t)bh * SEQ * HDIM;

    const int qrow = qt * 128 + tid;

    u64 q_p[32];
    {
        const ulonglong2* Qr = (const ulonglong2*)(Q + (size_t)qrow * HDIM);
#pragma unroll
        for (int t = 0; t < 16; t++) {
            ulonglong2 v = Qr[t];
            q_p[2 * t]     = v.x;
            q_p[2 * t + 1] = v.y;
        }
    }

    u64 o_p[32];
#pragma unroll
    for (int i = 0; i < 32; i++) o_p[i] = 0ull;
    float m = -1e30f;
    float l = 0.0f;

    __shared__ __align__(16) float Ks[32][64];
    __shared__ __align__(16) float Vs[32][64];

    const float scale = 0.125f;                 // 1/sqrt(64)
    const int kmax = qt * 128 + 128;            // exclusive

    // prefetch registers for the cooperative tile loads
    float4 kreg[4], vreg[4];
    {
        const float4* Kg = (const float4*)K;
        const float4* Vg = (const float4*)V;
#pragma unroll
        for (int it = 0; it < 4; it++) {
            kreg[it] = Kg[tid + it * 128];
            vreg[it] = Vg[tid + it * 128];
        }
    }

    for (int k0 = 0; k0 < kmax; k0 += 32) {
        __syncthreads();
        float4* Kss = (float4*)&Ks[0][0];
        float4* Vss = (float4*)&Vs[0][0];
#pragma unroll
        for (int it = 0; it < 4; it++) {
            Kss[tid + it * 128] = kreg[it];
            Vss[tid + it * 128] = vreg[it];
        }
        __syncthreads();

        if (k0 + 32 < kmax) {
            const float4* Kg = (const float4*)(K + (size_t)(k0 + 32) * HDIM);
            const float4* Vg = (const float4*)(V + (size_t)(k0 + 32) * HDIM);
#pragma unroll
            for (int it = 0; it < 4; it++) {
                kreg[it] = Kg[tid + it * 128];
                vreg[it] = Vg[tid + it * 128];
            }
        }

        if (k0 <= qrow) {
            float p[32];
            float mloc = m;
#pragma unroll 4
            for (int j = 0; j < 32; j++) {
                u64 d0 = 0ull, d1 = 0ull, d2 = 0ull, d3 = 0ull;
#pragma unroll
                for (int t = 0; t < 8; t++) {
                    ulonglong2 k0v = *(const ulonglong2*)&Ks[j][t * 8];
                    ulonglong2 k1v = *(const ulonglong2*)&Ks[j][t * 8 + 4];
                    fma2(d0, q_p[4 * t + 0], k0v.x);
                    fma2(d1, q_p[4 * t + 1], k0v.y);
                    fma2(d2, q_p[4 * t + 2], k1v.x);
                    fma2(d3, q_p[4 * t + 3], k1v.y);
                }
                u64 s01 = add2(d0, d1);
                u64 s23 = add2(d2, d3);
                float2 e = unpack2(add2(s01, s23));
                float dot = (e.x + e.y) * scale;
                if (k0 + j > qrow) dot = -1e30f;
                p[j] = dot;
                mloc = fmaxf(mloc, dot);
            }
            const float corr = __expf(m - mloc);
            float sum = 0.0f;
#pragma unroll 4
            for (int j = 0; j < 32; j++) {
                p[j] = __expf(p[j] - mloc);
                sum += p[j];
            }
            l = l * corr + sum;
            const u64 corr_p = pack2(corr, corr);
#pragma unroll
            for (int i = 0; i < 32; i++) o_p[i] = mul2(o_p[i], corr_p);
#pragma unroll 2
            for (int j = 0; j < 32; j++) {
                const u64 pj_p = pack2(p[j], p[j]);
#pragma unroll
                for (int t = 0; t < 8; t++) {
                    ulonglong2 v0 = *(const ulonglong2*)&Vs[j][t * 8];
                    ulonglong2 v1 = *(const ulonglong2*)&Vs[j][t * 8 + 4];
                    fma2(o_p[4 * t + 0], pj_p, v0.x);
                    fma2(o_p[4 * t + 1], pj_p, v0.y);
                    fma2(o_p[4 * t + 2], pj_p, v1.x);
                    fma2(o_p[4 * t + 3], pj_p, v1.y);
                }
            }
            m = mloc;
        }
    }

    const float invl = 1.0f / l;
    const int bb = bh >> 4;
    const int h = bh & (HEADS - 1);
    float* dst = g_attn + ((size_t)bb * SEQ + qrow) * DIM + h * HDIM;
#pragma unroll
    for (int t = 0; t < 16; t++) {
        float2 lo = unpack2(o_p[2 * t]);
        float2 hi = unpack2(o_p[2 * t + 1]);
        float4 v4;
        v4.x = lo.x * invl;
        v4.y = lo.y * invl;
        v4.z = hi.x * invl;
        v4.w = hi.y * invl;
        *(float4*)(dst + t * 4) = v4;
    }
}

// ---------------------------------------------------------------------------
// Output projection GEMM (4096 x 1024 x 1024) + bias -> d_out, packed f32x2.
// Reads g_attn directly as a device symbol.
// ---------------------------------------------------------------------------
__global__ __launch_bounds__(256) void out_gemm_kernel(
    const float* __restrict__ W,      // (1024, 1024)
    const float* __restrict__ bias,   // (1024,)
    float* __restrict__ out)          // (4096, 1024)
{
    __shared__ __align__(16) float As2[8][256];
    __shared__ __align__(16) float Bs[8][128];

    const float* A = g_attn;

    const int tid = threadIdx.x;
    const int tx = tid & 15;
    const int ty = tid >> 4;

    const int row0 = blockIdx.y * 128;
    const int col0 = blockIdx.x * 128;

    const int arow = tid >> 1;
    const int acol = (tid & 1) * 4;
    const int brow = tid >> 5;
    const int bcol = (tid & 31) * 4;

    const float* Aptr = A + (size_t)(row0 + arow) * DIM + acol;
    const float* Bptr = W + (size_t)brow * DIM + col0 + bcol;

    u64 acc_p[8][4];
#pragma unroll
    for (int i = 0; i < 8; i++)
#pragma unroll
        for (int j = 0; j < 4; j++) acc_p[i][j] = 0ull;

    float4 av = *(const float4*)(Aptr);
    float4 bv = *(const float4*)(Bptr);

    for (int k0 = 0; k0 < DIM; k0 += 8) {
        __syncthreads();
        *(u64*)&As2[acol + 0][2 * arow] = pack2(av.x, av.x);
        *(u64*)&As2[acol + 1][2 * arow] = pack2(av.y, av.y);
        *(u64*)&As2[acol + 2][2 * arow] = pack2(av.z, av.z);
        *(u64*)&As2[acol + 3][2 * arow] = pack2(av.w, av.w);
        *(float4*)&Bs[brow][bcol] = bv;
        __syncthreads();

        if (k0 + 8 < DIM) {
            av = *(const float4*)(Aptr + k0 + 8);
            bv = *(const float4*)(Bptr + (size_t)(k0 + 8) * DIM);
        }

#pragma unroll
        for (int kk = 0; kk < 8; kk++) {
            ulonglong2 a01 = *(const ulonglong2*)&As2[kk][2 * (ty * 8) + 0];
            ulonglong2 a23 = *(const ulonglong2*)&As2[kk][2 * (ty * 8) + 4];
            ulonglong2 a45 = *(const ulonglong2*)&As2[kk][2 * (ty * 8) + 8];
            ulonglong2 a67 = *(const ulonglong2*)&As2[kk][2 * (ty * 8) + 12];
            ulonglong2 bL = *(const ulonglong2*)&Bs[kk][tx * 8];
            ulonglong2 bH = *(const ulonglong2*)&Bs[kk][tx * 8 + 4];
            u64 ap[8] = {a01.x, a01.y, a23.x, a23.y, a45.x, a45.y, a67.x, a67.y};
            u64 bp[4] = {bL.x, bL.y, bH.x, bH.y};
#pragma unroll
            for (int i = 0; i < 8; i++)
#pragma unroll
                for (int j = 0; j < 4; j++)
                    fma2(acc_p[i][j], ap[i], bp[j]);
        }
    }

    float bi[8];
#pragma unroll
    for (int j = 0; j < 8; j++) bi[j] = bias[col0 + tx * 8 + j];

#pragma unroll
    for (int i = 0; i < 8; i++) {
        const int r = row0 + ty * 8 + i;
        float ac[8];
        float2 f;
        f = unpack2(acc_p[i][0]); ac[0] = f.x; ac[1] = f.y;
        f = unpack2(acc_p[i][1]); ac[2] = f.x; ac[3] = f.y;
        f = unpack2(acc_p[i][2]); ac[4] = f.x; ac[5] = f.y;
        f = unpack2(acc_p[i][3]); ac[6] = f.x; ac[7] = f.y;
        float4 v0, v1;
        v0.x = ac[0] + bi[0]; v0.y = ac[1] + bi[1];
        v0.z = ac[2] + bi[2]; v0.w = ac[3] + bi[3];
        v1.x = ac[4] + bi[4]; v1.y = ac[5] + bi[5];
        v1.z = ac[6] + bi[6]; v1.w = ac[7] + bi[7];
        *(float4*)&out[(size_t)r * DIM + col0 + tx * 8]     = v0;
        *(float4*)&out[(size_t)r * DIM + col0 + tx * 8 + 4] = v1;
    }
}

// ---------------------------------------------------------------------------
extern "C" void kernel_launch(void* const* d_in, const int* in_sizes, int n_in,
                              void* d_out, int out_size) {
    // Bind inputs by element count (robust to metadata ordering):
    const float* query = 0;
    const float* W_qkv = 0;
    const float* b_qkv = 0;
    const float* W_out = 0;
    const float* b_out = 0;
    for (int i = 0; i < n_in; i++) {
        switch (in_sizes[i]) {
            case 4194304: query = (const float*)d_in[i]; break;
            case 3145728: W_qkv = (const float*)d_in[i]; break;
            case 3072:    b_qkv = (const float*)d_in[i]; break;
            case 1048576: W_out = (const float*)d_in[i]; break;
            case 1024:    b_out = (const float*)d_in[i]; break;
        }
    }
    float* out = (float*)d_out;

    rope_table_kernel<<<(SEQ * 32 + 255) / 256, 256>>>();

    {
        dim3 grid(QKV_N / 128, NTOK / 128);       // (24, 32)
        qkv_rope_kernel<<<grid, 256>>>(query, W_qkv, b_qkv);
    }
    {
        dim3 grid(BATCH * HEADS, SEQ / 128);      // (32, 16)
        attn_kernel<<<grid, 128>>>();
    }
    {
        dim3 grid(DIM / 128, NTOK / 128);         // (8, 32)
        out_gemm_kernel<<<grid, 256>>>(W_out, b_out, out);
    }
}

// round 5
// speedup vs baseline: 1.5230x; 1.4862x over previous
#include <cuda_runtime.h>
#include <cuda_bf16.h>
#include <math.h>
#include <stdint.h>

#define BATCH 2
#define SEQ   2048
#define DIM   1024
#define HEADS 16
#define HDIM  64
#define NTOK  (BATCH*SEQ)          // 4096
#define QKV_N (3*DIM)              // 3072

typedef unsigned long long u64;

// ---- packed f32x2 helpers (attention kernel) ------------------------------
__device__ __forceinline__ u64 pack2(float lo, float hi) {
    u64 r; asm("mov.b64 %0, {%1, %2};" : "=l"(r) : "f"(lo), "f"(hi)); return r;
}
__device__ __forceinline__ float2 unpack2(u64 v) {
    float2 f; asm("mov.b64 {%0, %1}, %2;" : "=f"(f.x), "=f"(f.y) : "l"(v)); return f;
}
__device__ __forceinline__ void fma2(u64 &d, u64 a, u64 b) {
    asm("fma.rn.f32x2 %0, %1, %2, %0;" : "+l"(d) : "l"(a), "l"(b));
}
__device__ __forceinline__ u64 mul2(u64 a, u64 b) {
    u64 r; asm("mul.rn.f32x2 %0, %1, %2;" : "=l"(r) : "l"(a), "l"(b)); return r;
}
__device__ __forceinline__ u64 add2(u64 a, u64 b) {
    u64 r; asm("add.rn.f32x2 %0, %1, %2;" : "=l"(r) : "l"(a), "l"(b)); return r;
}

// ---- warp-mma helpers (all base-PTX, no 'a' features) ----------------------
__device__ __forceinline__ uint32_t s2u32(const void* p) {
    uint32_t a;
    asm("{ .reg .u64 t; cvta.to.shared.u64 t, %1; cvt.u32.u64 %0, t; }" : "=r"(a) : "l"(p));
    return a;
}
__device__ __forceinline__ void ldsm_x4(uint32_t* r, uint32_t addr) {
    asm volatile("ldmatrix.sync.aligned.m8n8.x4.shared.b16 {%0,%1,%2,%3}, [%4];"
                 : "=r"(r[0]), "=r"(r[1]), "=r"(r[2]), "=r"(r[3]) : "r"(addr));
}
__device__ __forceinline__ void mma_bf16(float* c, const uint32_t* a, const uint32_t* b) {
    asm volatile(
        "mma.sync.aligned.m16n8k16.row.col.f32.bf16.bf16.f32 "
        "{%0,%1,%2,%3},{%4,%5,%6,%7},{%8,%9},{%0,%1,%2,%3};"
        : "+f"(c[0]), "+f"(c[1]), "+f"(c[2]), "+f"(c[3])
        : "r"(a[0]), "r"(a[1]), "r"(a[2]), "r"(a[3]), "r"(b[0]), "r"(b[1]));
}
__device__ __forceinline__ void cpa16(uint32_t dst, const void* src) {
    asm volatile("cp.async.cg.shared.global [%0], [%1], 16;" :: "r"(dst), "l"(src) : "memory");
}
#define CP_COMMIT() asm volatile("cp.async.commit_group;" ::: "memory")
#define CP_WAIT(n)  asm volatile("cp.async.wait_group %0;" :: "n"(n) : "memory")

// SW64 swizzle for 64-byte rows (BK=32 bf16): XOR addr bits [5:4] with row bits [2:1]
__device__ __forceinline__ uint32_t swzoff(int row, int kb) {
    return (uint32_t)(row * 64 + (kb ^ ((row & 6) << 3)));
}

// ---- device scratch --------------------------------------------------------
__device__ float g_q[BATCH*HEADS*SEQ*HDIM];     // (B,H,S,HD)
__device__ float g_k[BATCH*HEADS*SEQ*HDIM];
__device__ float g_v[BATCH*HEADS*SEQ*HDIM];
__device__ float g_cos[SEQ*32];
__device__ float g_sin[SEQ*32];
__device__ __nv_bfloat16 g_xhi[NTOK*DIM],  g_xlo[NTOK*DIM];          // split(X)
__device__ __nv_bfloat16 g_wqT_hi[QKV_N*DIM], g_wqT_lo[QKV_N*DIM];   // split(W_qkv^T) (N,K)
__device__ __nv_bfloat16 g_woT_hi[DIM*DIM],   g_woT_lo[DIM*DIM];     // split(W_out^T) (N,K)
__device__ __nv_bfloat16 g_ahi[NTOK*DIM],  g_alo[NTOK*DIM];          // split(attn out) (B,S,D)

// ---------------------------------------------------------------------------
// RoPE table (fp64 sincos for accuracy)
// ---------------------------------------------------------------------------
__global__ void rope_table_kernel() {
    int idx = blockIdx.x * blockDim.x + threadIdx.x;
    if (idx >= SEQ * 32) return;
    int s = idx >> 5;
    int j = idx & 31;
    double theta = (double)s * pow(10000.0, -(double)j / 32.0);
    double sc, cc;
    sincos(theta, &sc, &cc);
    g_cos[idx] = (float)cc;
    g_sin[idx] = (float)sc;
}

// ---------------------------------------------------------------------------
// Split X (fp32) -> bf16 hi/lo
// ---------------------------------------------------------------------------
__global__ __launch_bounds__(256) void split_x_kernel(const float* __restrict__ X) {
    int i = (blockIdx.x * 256 + threadIdx.x) * 4;
    float4 v = *(const float4*)(X + i);
    float a[4] = {v.x, v.y, v.z, v.w};
    __nv_bfloat16 h[4], l[4];
#pragma unroll
    for (int j = 0; j < 4; j++) {
        h[j] = __float2bfloat16(a[j]);
        l[j] = __float2bfloat16(a[j] - __bfloat162float(h[j]));
    }
    __nv_bfloat162* dh = (__nv_bfloat162*)(g_xhi + i);
    __nv_bfloat162* dl = (__nv_bfloat162*)(g_xlo + i);
    dh[0] = __halves2bfloat162(h[0], h[1]);
    dh[1] = __halves2bfloat162(h[2], h[3]);
    dl[0] = __halves2bfloat162(l[0], l[1]);
    dl[1] = __halves2bfloat162(l[2], l[3]);
}

// ---------------------------------------------------------------------------
// Transpose + split weights: W (K=1024, N) row-major -> W^T (N, K=1024) bf16 hi/lo
// ---------------------------------------------------------------------------
__global__ void transpose_split_kernel(const float* __restrict__ W, int which) {
    __shared__ float t32[32][33];
    const int N = which ? DIM : QKV_N;
    __nv_bfloat16* Th = which ? g_woT_hi : g_wqT_hi;
    __nv_bfloat16* Tl = which ? g_woT_lo : g_wqT_lo;
    const int n0 = blockIdx.x * 32, k0 = blockIdx.y * 32;
    const int tx = threadIdx.x, ty = threadIdx.y;       // (32, 8)
#pragma unroll
    for (int i = 0; i < 4; i++)
        t32[ty + 8 * i][tx] = W[(size_t)(k0 + ty + 8 * i) * N + n0 + tx];
    __syncthreads();
#pragma unroll
    for (int i = 0; i < 4; i++) {
        float v = t32[tx][ty + 8 * i];                  // = W[k0+tx][n0+ty+8i]
        __nv_bfloat16 h = __float2bfloat16(v);
        size_t o = (size_t)(n0 + ty + 8 * i) * DIM + k0 + tx;
        Th[o] = h;
        Tl[o] = __float2bfloat16(v - __bfloat162float(h));
    }
}

// ---------------------------------------------------------------------------
// Warp-MMA split-bf16 GEMM: D(fp32) = Ah*Bh + Ah*Bl + Al*Bh  (+bias, epilogue)
// CTA 128x128, 8 warps (2x4), warp tile 64x32, BK=32, double-buffered cp.async.
// MODE 0: A=X split, B=W_qkv^T split, epilogue bias+RoPE -> g_q/g_k/g_v
// MODE 1: A=attn split, B=W_out^T split, epilogue bias -> outp
// ---------------------------------------------------------------------------
#define TB_SZ   8192              // one 128x32 bf16 tile
#define OFF_AH  0
#define OFF_AL  8192
#define OFF_BH  16384
#define OFF_BL  24576
#define BUF_SZ  32768
#define GSMEM   69632             // max(2*BUF_SZ, 128*132*4 staging)

template<int MODE>
__global__ __launch_bounds__(256) void mma_gemm_kernel(const float* __restrict__ bias,
                                                       float* __restrict__ outp) {
    extern __shared__ __align__(16) char sm[];
    const uint32_t smb = s2u32(sm);
    const int tid  = threadIdx.x;
    const int wid  = tid >> 5;
    const int lane = tid & 31;
    const int warp_m = wid >> 2;     // 0..1
    const int warp_n = wid & 3;      // 0..3

    const int n0 = blockIdx.x * 128;
    const int m0 = blockIdx.y * 128;

    const __nv_bfloat16* __restrict__ Ah = (MODE == 0) ? g_xhi : g_ahi;
    const __nv_bfloat16* __restrict__ Al = (MODE == 0) ? g_xlo : g_alo;
    const __nv_bfloat16* __restrict__ Bh = (MODE == 0) ? g_wqT_hi : g_woT_hi;
    const __nv_bfloat16* __restrict__ Bl = (MODE == 0) ? g_wqT_lo : g_woT_lo;

    float c[4][4][4];
#pragma unroll
    for (int i = 0; i < 4; i++)
#pragma unroll
        for (int j = 0; j < 4; j++)
#pragma unroll
            for (int r = 0; r < 4; r++) c[i][j][r] = 0.0f;

    // cp.async tile issue: per matrix 512 x 16B, 256 threads -> 2 each
    const int ld_row = tid >> 2;            // 0..63 (plus +64 on second pass)
    const int ld_kb  = (tid & 3) * 16;      // byte offset within 64B row

#define ISSUE_CHUNK(chunk, buf) do {                                           \
    const int k0e = (chunk) * 32;                                              \
    const uint32_t bb = smb + (buf) * BUF_SZ;                                  \
    _Pragma("unroll")                                                          \
    for (int m = 0; m < 2; m++) {                                              \
        const int row = ld_row + m * 64;                                       \
        const uint32_t so = swzoff(row, ld_kb);                                \
        const char* pa = (const char*)(Ah + (size_t)(m0 + row) * DIM + k0e) + ld_kb; \
        const char* pl = (const char*)(Al + (size_t)(m0 + row) * DIM + k0e) + ld_kb; \
        const char* pb = (const char*)(Bh + (size_t)(n0 + row) * DIM + k0e) + ld_kb; \
        const char* pc = (const char*)(Bl + (size_t)(n0 + row) * DIM + k0e) + ld_kb; \
        cpa16(bb + OFF_AH + so, pa);                                           \
        cpa16(bb + OFF_AL + so, pl);                                           \
        cpa16(bb + OFF_BH + so, pb);                                           \
        cpa16(bb + OFF_BL + so, pc);                                           \
    }                                                                          \
} while (0)

    ISSUE_CHUNK(0, 0);
    CP_COMMIT();

    for (int ch = 0; ch < 32; ch++) {
        const int buf = ch & 1;
        if (ch + 1 < 32) {
            ISSUE_CHUNK(ch + 1, buf ^ 1);
            CP_COMMIT();
            CP_WAIT(1);
        } else {
            CP_WAIT(0);
        }
        __syncthreads();

        const uint32_t bb = smb + buf * BUF_SZ;
#pragma unroll
        for (int ks = 0; ks < 2; ks++) {
            uint32_t ah[4][4], al[4][4];
#pragma unroll
            for (int i = 0; i < 4; i++) {
                const int row = warp_m * 64 + 16 * i + (lane & 7) + ((lane >> 3) & 1) * 8;
                const int kb  = ks * 32 + (lane >> 4) * 16;
                const uint32_t so = swzoff(row, kb);
                ldsm_x4(ah[i], bb + OFF_AH + so);
                ldsm_x4(al[i], bb + OFF_AL + so);
            }
            uint32_t bh[4][2], bl[4][2];
#pragma unroll
            for (int j2 = 0; j2 < 2; j2++) {
                const int row = warp_n * 32 + 16 * j2 + (lane & 7) + ((lane >> 4) & 1) * 8;
                const int kb  = ks * 32 + ((lane >> 3) & 1) * 16;
                const uint32_t so = swzoff(row, kb);
                uint32_t r[4];
                ldsm_x4(r, bb + OFF_BH + so);
                bh[2 * j2][0] = r[0]; bh[2 * j2][1] = r[1];
                bh[2 * j2 + 1][0] = r[2]; bh[2 * j2 + 1][1] = r[3];
                ldsm_x4(r, bb + OFF_BL + so);
                bl[2 * j2][0] = r[0]; bl[2 * j2][1] = r[1];
                bl[2 * j2 + 1][0] = r[2]; bl[2 * j2 + 1][1] = r[3];
            }
#pragma unroll
            for (int i = 0; i < 4; i++)
#pragma unroll
                for (int j = 0; j < 4; j++) {
                    mma_bf16(c[i][j], ah[i], bh[j]);
                    mma_bf16(c[i][j], ah[i], bl[j]);
                    mma_bf16(c[i][j], al[i], bh[j]);
                }
        }
        __syncthreads();
    }

    if (MODE == 1) {
        // direct fragment stores + bias
#pragma unroll
        for (int i = 0; i < 4; i++) {
            const int row = m0 + warp_m * 64 + 16 * i + (lane >> 2);
#pragma unroll
            for (int j = 0; j < 4; j++) {
                const int col = n0 + warp_n * 32 + 8 * j + (lane & 3) * 2;
                const float b0 = bias[col], b1 = bias[col + 1];
                float2 v0 = make_float2(c[i][j][0] + b0, c[i][j][1] + b1);
                float2 v1 = make_float2(c[i][j][2] + b0, c[i][j][3] + b1);
                *(float2*)&outp[(size_t)row * DIM + col]       = v0;
                *(float2*)&outp[(size_t)(row + 8) * DIM + col] = v1;
            }
        }
        return;
    }

    // MODE 0: stage to smem so RoPE pairs (d, d+32) are in one thread
    float* st = (float*)sm;                 // 128 rows x 132 stride
#pragma unroll
    for (int i = 0; i < 4; i++) {
        const int rl = warp_m * 64 + 16 * i + (lane >> 2);
#pragma unroll
        for (int j = 0; j < 4; j++) {
            const int cl = warp_n * 32 + 8 * j + (lane & 3) * 2;
            st[rl * 132 + cl]           = c[i][j][0];
            st[rl * 132 + cl + 1]       = c[i][j][1];
            st[(rl + 8) * 132 + cl]     = c[i][j][2];
            st[(rl + 8) * 132 + cl + 1] = c[i][j][3];
        }
    }
    __syncthreads();

    const int comp = n0 >> 10;               // 0=q 1=k 2=v
    float* dstg = (comp == 0) ? g_q : (comp == 1) ? g_k : g_v;
    const int r  = tid >> 1;
    const int hl = tid & 1;
    const int token = m0 + r;
    const int s  = token & (SEQ - 1);
    const int bb = token >> 11;
    const int gh = ((n0 + hl * 64) >> 6) & (HEADS - 1);
    float* dp = dstg + (((size_t)bb * HEADS + gh) * SEQ + s) * HDIM;
    const float* brow = bias + n0 + hl * 64;
    const float* srow = st + r * 132 + hl * 64;

    if (comp < 2) {
#pragma unroll
        for (int d4 = 0; d4 < 8; d4++) {
            const int d = 4 * d4;
            float4 x1 = *(const float4*)(srow + d);
            float4 x2 = *(const float4*)(srow + 32 + d);
            float4 b1 = *(const float4*)(brow + d);
            float4 b2 = *(const float4*)(brow + 32 + d);
            float4 cs = *(const float4*)(g_cos + s * 32 + d);
            float4 sn = *(const float4*)(g_sin + s * 32 + d);
            x1.x += b1.x; x1.y += b1.y; x1.z += b1.z; x1.w += b1.w;
            x2.x += b2.x; x2.y += b2.y; x2.z += b2.z; x2.w += b2.w;
            float4 lo, hi;
            lo.x = x1.x * cs.x - x2.x * sn.x;  hi.x = x2.x * cs.x + x1.x * sn.x;
            lo.y = x1.y * cs.y - x2.y * sn.y;  hi.y = x2.y * cs.y + x1.y * sn.y;
            lo.z = x1.z * cs.z - x2.z * sn.z;  hi.z = x2.z * cs.z + x1.z * sn.z;
            lo.w = x1.w * cs.w - x2.w * sn.w;  hi.w = x2.w * cs.w + x1.w * sn.w;
            *(float4*)(dp + d)      = lo;
            *(float4*)(dp + 32 + d) = hi;
        }
    } else {
#pragma unroll
        for (int d4 = 0; d4 < 16; d4++) {
            const int d = 4 * d4;
            float4 x = *(const float4*)(srow + d);
            float4 b = *(const float4*)(brow + d);
            x.x += b.x; x.y += b.y; x.z += b.z; x.w += b.w;
            *(float4*)(dp + d) = x;
        }
    }
#undef ISSUE_CHUNK
}

// ---------------------------------------------------------------------------
// Flash attention (FFMA2), epilogue writes split bf16 hi/lo for the out-proj.
// ---------------------------------------------------------------------------
__global__ __launch_bounds__(128) void attn_kernel() {
    const int bh = blockIdx.x;                  // 0..31
    const int qt = blockIdx.y;                  // 0..15
    const int tid = threadIdx.x;

    const float* Q = g_q + (size_t)bh * SEQ * HDIM;
    const float* K = g_k + (size_t)bh * SEQ * HDIM;
    const float* V = g_v + (size_t)bh * SEQ * HDIM;

    const int qrow = qt * 128 + tid;

    u64 q_p[32];
    {
        const ulonglong2* Qr = (const ulonglong2*)(Q + (size_t)qrow * HDIM);
#pragma unroll
        for (int t = 0; t < 16; t++) {
            ulonglong2 v = Qr[t];
            q_p[2 * t]     = v.x;
            q_p[2 * t + 1] = v.y;
        }
    }

    u64 o_p[32];
#pragma unroll
    for (int i = 0; i < 32; i++) o_p[i] = 0ull;
    float m = -1e30f;
    float l = 0.0f;

    __shared__ __align__(16) float Ks[32][64];
    __shared__ __align__(16) float Vs[32][64];

    const float scale = 0.125f;
    const int kmax = qt * 128 + 128;

    float4 kreg[4], vreg[4];
    {
        const float4* Kg = (const float4*)K;
        const float4* Vg = (const float4*)V;
#pragma unroll
        for (int it = 0; it < 4; it++) {
            kreg[it] = Kg[tid + it * 128];
            vreg[it] = Vg[tid + it * 128];
        }
    }

    for (int k0 = 0; k0 < kmax; k0 += 32) {
        __syncthreads();
        float4* Kss = (float4*)&Ks[0][0];
        float4* Vss = (float4*)&Vs[0][0];
#pragma unroll
        for (int it = 0; it < 4; it++) {
            Kss[tid + it * 128] = kreg[it];
            Vss[tid + it * 128] = vreg[it];
        }
        __syncthreads();

        if (k0 + 32 < kmax) {
            const float4* Kg = (const float4*)(K + (size_t)(k0 + 32) * HDIM);
            const float4* Vg = (const float4*)(V + (size_t)(k0 + 32) * HDIM);
#pragma unroll
            for (int it = 0; it < 4; it++) {
                kreg[it] = Kg[tid + it * 128];
                vreg[it] = Vg[tid + it * 128];
            }
        }

        if (k0 <= qrow) {
            float p[32];
            float mloc = m;
#pragma unroll 4
            for (int j = 0; j < 32; j++) {
                u64 d0 = 0ull, d1 = 0ull, d2 = 0ull, d3 = 0ull;
#pragma unroll
                for (int t = 0; t < 8; t++) {
                    ulonglong2 k0v = *(const ulonglong2*)&Ks[j][t * 8];
                    ulonglong2 k1v = *(const ulonglong2*)&Ks[j][t * 8 + 4];
                    fma2(d0, q_p[4 * t + 0], k0v.x);
                    fma2(d1, q_p[4 * t + 1], k0v.y);
                    fma2(d2, q_p[4 * t + 2], k1v.x);
                    fma2(d3, q_p[4 * t + 3], k1v.y);
                }
                u64 s01 = add2(d0, d1);
                u64 s23 = add2(d2, d3);
                float2 e = unpack2(add2(s01, s23));
                float dot = (e.x + e.y) * scale;
                if (k0 + j > qrow) dot = -1e30f;
                p[j] = dot;
                mloc = fmaxf(mloc, dot);
            }
            const float corr = __expf(m - mloc);
            float sum = 0.0f;
#pragma unroll 4
            for (int j = 0; j < 32; j++) {
                p[j] = __expf(p[j] - mloc);
                sum += p[j];
            }
            l = l * corr + sum;
            const u64 corr_p = pack2(corr, corr);
#pragma unroll
            for (int i = 0; i < 32; i++) o_p[i] = mul2(o_p[i], corr_p);
#pragma unroll 2
            for (int j = 0; j < 32; j++) {
                const u64 pj_p = pack2(p[j], p[j]);
#pragma unroll
                for (int t = 0; t < 8; t++) {
                    ulonglong2 v0 = *(const ulonglong2*)&Vs[j][t * 8];
                    ulonglong2 v1 = *(const ulonglong2*)&Vs[j][t * 8 + 4];
                    fma2(o_p[4 * t + 0], pj_p, v0.x);
                    fma2(o_p[4 * t + 1], pj_p, v0.y);
                    fma2(o_p[4 * t + 2], pj_p, v1.x);
                    fma2(o_p[4 * t + 3], pj_p, v1.y);
                }
            }
            m = mloc;
        }
    }

    const float invl = 1.0f / l;
    const int bb = bh >> 4;
    const int hh = bh & (HEADS - 1);
    const size_t base = ((size_t)bb * SEQ + qrow) * DIM + hh * HDIM;
    __nv_bfloat162* dh = (__nv_bfloat162*)(g_ahi + base);
    __nv_bfloat162* dl = (__nv_bfloat162*)(g_alo + base);
#pragma unroll
    for (int t = 0; t < 16; t++) {
        float2 lo2 = unpack2(o_p[2 * t]);
        float2 hi2 = unpack2(o_p[2 * t + 1]);
        float v0 = lo2.x * invl, v1 = lo2.y * invl, v2 = hi2.x * invl, v3 = hi2.y * invl;
        __nv_bfloat16 h0 = __float2bfloat16(v0), h1 = __float2bfloat16(v1);
        __nv_bfloat16 h2 = __float2bfloat16(v2), h3 = __float2bfloat16(v3);
        __nv_bfloat16 l0 = __float2bfloat16(v0 - __bfloat162float(h0));
        __nv_bfloat16 l1 = __float2bfloat16(v1 - __bfloat162float(h1));
        __nv_bfloat16 l2 = __float2bfloat16(v2 - __bfloat162float(h2));
        __nv_bfloat16 l3 = __float2bfloat16(v3 - __bfloat162float(h3));
        dh[2 * t]     = __halves2bfloat162(h0, h1);
        dh[2 * t + 1] = __halves2bfloat162(h2, h3);
        dl[2 * t]     = __halves2bfloat162(l0, l1);
        dl[2 * t + 1] = __halves2bfloat162(l2, l3);
    }
}

// ---------------------------------------------------------------------------
extern "C" void kernel_launch(void* const* d_in, const int* in_sizes, int n_in,
                              void* d_out, int out_size) {
    const float* query = 0;
    const float* W_qkv = 0;
    const float* b_qkv = 0;
    const float* W_out = 0;
    const float* b_out = 0;
    for (int i = 0; i < n_in; i++) {
        switch (in_sizes[i]) {
            case 4194304: query = (const float*)d_in[i]; break;
            case 3145728: W_qkv = (const float*)d_in[i]; break;
            case 3072:    b_qkv = (const float*)d_in[i]; break;
            case 1048576: W_out = (const float*)d_in[i]; break;
            case 1024:    b_out = (const float*)d_in[i]; break;
        }
    }
    float* out = (float*)d_out;

    cudaFuncSetAttribute(mma_gemm_kernel<0>, cudaFuncAttributeMaxDynamicSharedMemorySize, GSMEM);
    cudaFuncSetAttribute(mma_gemm_kernel<1>, cudaFuncAttributeMaxDynamicSharedMemorySize, GSMEM);

    rope_table_kernel<<<(SEQ * 32 + 255) / 256, 256>>>();
    split_x_kernel<<<NTOK * DIM / 1024, 256>>>(query);
    transpose_split_kernel<<<dim3(QKV_N / 32, DIM / 32), dim3(32, 8)>>>(W_qkv, 0);
    transpose_split_kernel<<<dim3(DIM / 32, DIM / 32), dim3(32, 8)>>>(W_out, 1);

    mma_gemm_kernel<0><<<dim3(QKV_N / 128, NTOK / 128), 256, GSMEM>>>(b_qkv, nullptr);

    attn_kernel<<<dim3(BATCH * HEADS, SEQ / 128), 128>>>();

    mma_gemm_kernel<1><<<dim3(DIM / 128, NTOK / 128), 256, GSMEM>>>(b_out, out);
}

// round 6
// speedup vs baseline: 2.7686x; 1.8178x over previous
#include <cuda_runtime.h>
#include <cuda_bf16.h>
#include <math.h>
#include <stdint.h>

#define BATCH 2
#define SEQ   2048
#define DIM   1024
#define HEADS 16
#define HDIM  64
#define NTOK  (BATCH*SEQ)          // 4096
#define QKV_N (3*DIM)              // 3072

typedef unsigned long long u64;

// 0.125 * log2(e): folds attention scale + base-2 softmax into q
#define S0F 0.18033688011112042f

// ---- helpers (all base-PTX, no 'a' features) --------------------------------
__device__ __forceinline__ uint32_t s2u32(const void* p) {
    uint32_t a;
    asm("{ .reg .u64 t; cvta.to.shared.u64 t, %1; cvt.u32.u64 %0, t; }" : "=r"(a) : "l"(p));
    return a;
}
__device__ __forceinline__ void ldsm_x4(uint32_t* r, uint32_t addr) {
    asm volatile("ldmatrix.sync.aligned.m8n8.x4.shared.b16 {%0,%1,%2,%3}, [%4];"
                 : "=r"(r[0]), "=r"(r[1]), "=r"(r[2]), "=r"(r[3]) : "r"(addr));
}
__device__ __forceinline__ void ldsm_x4_t(uint32_t* r, uint32_t addr) {
    asm volatile("ldmatrix.sync.aligned.m8n8.x4.trans.shared.b16 {%0,%1,%2,%3}, [%4];"
                 : "=r"(r[0]), "=r"(r[1]), "=r"(r[2]), "=r"(r[3]) : "r"(addr));
}
__device__ __forceinline__ void mma_bf16(float* c, const uint32_t* a, const uint32_t* b) {
    asm volatile(
        "mma.sync.aligned.m16n8k16.row.col.f32.bf16.bf16.f32 "
        "{%0,%1,%2,%3},{%4,%5,%6,%7},{%8,%9},{%0,%1,%2,%3};"
        : "+f"(c[0]), "+f"(c[1]), "+f"(c[2]), "+f"(c[3])
        : "r"(a[0]), "r"(a[1]), "r"(a[2]), "r"(a[3]), "r"(b[0]), "r"(b[1]));
}
__device__ __forceinline__ void cpa16(uint32_t dst, const void* src) {
    asm volatile("cp.async.cg.shared.global [%0], [%1], 16;" :: "r"(dst), "l"(src) : "memory");
}
#define CP_COMMIT() asm volatile("cp.async.commit_group;" ::: "memory")
#define CP_WAIT(n)  asm volatile("cp.async.wait_group %0;" :: "n"(n) : "memory")

__device__ __forceinline__ float ex2f(float x) {
    float r; asm("ex2.approx.f32 %0, %1;" : "=f"(r) : "f"(x)); return r;
}
__device__ __forceinline__ uint32_t bf2u(__nv_bfloat16 a, __nv_bfloat16 b) {
    __nv_bfloat162 t = __halves2bfloat162(a, b);
    return *(uint32_t*)&t;
}

// SW64 swizzle for 64-byte rows (GEMM tiles, BK=32 bf16)
__device__ __forceinline__ uint32_t swzoff(int row, int kb) {
    return (uint32_t)(row * 64 + (kb ^ ((row & 6) << 3)));
}
// SW128-ish swizzle for 128-byte rows (attention tiles, 64 bf16/row)
__device__ __forceinline__ uint32_t swz128(int row, int cb) {
    return (uint32_t)(row * 128 + (cb ^ ((row & 7) << 4)));
}

// ---- device scratch ----------------------------------------------------------
__device__ float g_cos[SEQ*32];
__device__ float g_sin[SEQ*32];
__device__ __nv_bfloat16 g_xhi[NTOK*DIM],  g_xlo[NTOK*DIM];          // split(X)
__device__ __nv_bfloat16 g_wqT_hi[QKV_N*DIM], g_wqT_lo[QKV_N*DIM];   // split(W_qkv^T)
__device__ __nv_bfloat16 g_woT_hi[DIM*DIM],   g_woT_lo[DIM*DIM];     // split(W_out^T)
__device__ __nv_bfloat16 g_qhi[BATCH*HEADS*SEQ*HDIM], g_qlo[BATCH*HEADS*SEQ*HDIM];
__device__ __nv_bfloat16 g_khi[BATCH*HEADS*SEQ*HDIM], g_klo[BATCH*HEADS*SEQ*HDIM];
__device__ __nv_bfloat16 g_vhi[BATCH*HEADS*SEQ*HDIM], g_vlo[BATCH*HEADS*SEQ*HDIM];
__device__ __nv_bfloat16 g_ahi[NTOK*DIM],  g_alo[NTOK*DIM];          // split(attn out)

// ---------------------------------------------------------------------------
// RoPE table (fp64 sincos for accuracy)
// ---------------------------------------------------------------------------
__global__ void rope_table_kernel() {
    int idx = blockIdx.x * blockDim.x + threadIdx.x;
    if (idx >= SEQ * 32) return;
    int s = idx >> 5;
    int j = idx & 31;
    double theta = (double)s * pow(10000.0, -(double)j / 32.0);
    double sc, cc;
    sincos(theta, &sc, &cc);
    g_cos[idx] = (float)cc;
    g_sin[idx] = (float)sc;
}

// ---------------------------------------------------------------------------
// Split X (fp32) -> bf16 hi/lo
// ---------------------------------------------------------------------------
__global__ __launch_bounds__(256) void split_x_kernel(const float* __restrict__ X) {
    int i = (blockIdx.x * 256 + threadIdx.x) * 4;
    float4 v = *(const float4*)(X + i);
    float a[4] = {v.x, v.y, v.z, v.w};
    __nv_bfloat16 h[4], l[4];
#pragma unroll
    for (int j = 0; j < 4; j++) {
        h[j] = __float2bfloat16(a[j]);
        l[j] = __float2bfloat16(a[j] - __bfloat162float(h[j]));
    }
    *(uint32_t*)(g_xhi + i)     = bf2u(h[0], h[1]);
    *(uint32_t*)(g_xhi + i + 2) = bf2u(h[2], h[3]);
    *(uint32_t*)(g_xlo + i)     = bf2u(l[0], l[1]);
    *(uint32_t*)(g_xlo + i + 2) = bf2u(l[2], l[3]);
}

// ---------------------------------------------------------------------------
// Transpose + split weights: W (K=1024, N) row-major -> W^T (N, K=1024) hi/lo
// ---------------------------------------------------------------------------
__global__ void transpose_split_kernel(const float* __restrict__ W, int which) {
    __shared__ float t32[32][33];
    const int N = which ? DIM : QKV_N;
    __nv_bfloat16* Th = which ? g_woT_hi : g_wqT_hi;
    __nv_bfloat16* Tl = which ? g_woT_lo : g_wqT_lo;
    const int n0 = blockIdx.x * 32, k0 = blockIdx.y * 32;
    const int tx = threadIdx.x, ty = threadIdx.y;       // (32, 8)
#pragma unroll
    for (int i = 0; i < 4; i++)
        t32[ty + 8 * i][tx] = W[(size_t)(k0 + ty + 8 * i) * N + n0 + tx];
    __syncthreads();
#pragma unroll
    for (int i = 0; i < 4; i++) {
        float v = t32[tx][ty + 8 * i];
        __nv_bfloat16 h = __float2bfloat16(v);
        size_t o = (size_t)(n0 + ty + 8 * i) * DIM + k0 + tx;
        Th[o] = h;
        Tl[o] = __float2bfloat16(v - __bfloat162float(h));
    }
}

// ---------------------------------------------------------------------------
// Warp-MMA split-bf16 GEMM (same core as round 5; epilogues write bf16 splits)
// MODE 0: X @ W_qkv + bias, RoPE, q scaled by S0F -> g_{q,k,v}{hi,lo}
// MODE 1: attn @ W_out + bias -> outp (fp32)
// ---------------------------------------------------------------------------
#define OFF_AH  0
#define OFF_AL  8192
#define OFF_BH  16384
#define OFF_BL  24576
#define BUF_SZ  32768
#define GSMEM   69632

template<int MODE>
__global__ __launch_bounds__(256) void mma_gemm_kernel(const float* __restrict__ bias,
                                                       float* __restrict__ outp) {
    extern __shared__ __align__(16) char sm[];
    const uint32_t smb = s2u32(sm);
    const int tid  = threadIdx.x;
    const int wid  = tid >> 5;
    const int lane = tid & 31;
    const int warp_m = wid >> 2;
    const int warp_n = wid & 3;

    const int n0 = blockIdx.x * 128;
    const int m0 = blockIdx.y * 128;

    const __nv_bfloat16* __restrict__ Ah = (MODE == 0) ? g_xhi : g_ahi;
    const __nv_bfloat16* __restrict__ Al = (MODE == 0) ? g_xlo : g_alo;
    const __nv_bfloat16* __restrict__ Bh = (MODE == 0) ? g_wqT_hi : g_woT_hi;
    const __nv_bfloat16* __restrict__ Bl = (MODE == 0) ? g_wqT_lo : g_woT_lo;

    float c[4][4][4];
#pragma unroll
    for (int i = 0; i < 4; i++)
#pragma unroll
        for (int j = 0; j < 4; j++)
#pragma unroll
            for (int r = 0; r < 4; r++) c[i][j][r] = 0.0f;

    const int ld_row = tid >> 2;
    const int ld_kb  = (tid & 3) * 16;

#define ISSUE_CHUNK(chunk, buf) do {                                           \
    const int k0e = (chunk) * 32;                                              \
    const uint32_t bb = smb + (buf) * BUF_SZ;                                  \
    _Pragma("unroll")                                                          \
    for (int m = 0; m < 2; m++) {                                              \
        const int row = ld_row + m * 64;                                       \
        const uint32_t so = swzoff(row, ld_kb);                                \
        cpa16(bb + OFF_AH + so, (const char*)(Ah + (size_t)(m0 + row) * DIM + k0e) + ld_kb); \
        cpa16(bb + OFF_AL + so, (const char*)(Al + (size_t)(m0 + row) * DIM + k0e) + ld_kb); \
        cpa16(bb + OFF_BH + so, (const char*)(Bh + (size_t)(n0 + row) * DIM + k0e) + ld_kb); \
        cpa16(bb + OFF_BL + so, (const char*)(Bl + (size_t)(n0 + row) * DIM + k0e) + ld_kb); \
    }                                                                          \
} while (0)

    ISSUE_CHUNK(0, 0);
    CP_COMMIT();

    for (int ch = 0; ch < 32; ch++) {
        const int buf = ch & 1;
        if (ch + 1 < 32) {
            ISSUE_CHUNK(ch + 1, buf ^ 1);
            CP_COMMIT();
            CP_WAIT(1);
        } else {
            CP_WAIT(0);
        }
        __syncthreads();

        const uint32_t bb = smb + buf * BUF_SZ;
#pragma unroll
        for (int ks = 0; ks < 2; ks++) {
            uint32_t ah[4][4], al[4][4];
#pragma unroll
            for (int i = 0; i < 4; i++) {
                const int row = warp_m * 64 + 16 * i + (lane & 7) + ((lane >> 3) & 1) * 8;
                const int kb  = ks * 32 + (lane >> 4) * 16;
                const uint32_t so = swzoff(row, kb);
                ldsm_x4(ah[i], bb + OFF_AH + so);
                ldsm_x4(al[i], bb + OFF_AL + so);
            }
            uint32_t bh[4][2], bl[4][2];
#pragma unroll
            for (int j2 = 0; j2 < 2; j2++) {
                const int row = warp_n * 32 + 16 * j2 + (lane & 7) + ((lane >> 4) & 1) * 8;
                const int kb  = ks * 32 + ((lane >> 3) & 1) * 16;
                const uint32_t so = swzoff(row, kb);
                uint32_t r[4];
                ldsm_x4(r, bb + OFF_BH + so);
                bh[2 * j2][0] = r[0]; bh[2 * j2][1] = r[1];
                bh[2 * j2 + 1][0] = r[2]; bh[2 * j2 + 1][1] = r[3];
                ldsm_x4(r, bb + OFF_BL + so);
                bl[2 * j2][0] = r[0]; bl[2 * j2][1] = r[1];
                bl[2 * j2 + 1][0] = r[2]; bl[2 * j2 + 1][1] = r[3];
            }
#pragma unroll
            for (int i = 0; i < 4; i++)
#pragma unroll
                for (int j = 0; j < 4; j++) {
                    mma_bf16(c[i][j], ah[i], bh[j]);
                    mma_bf16(c[i][j], ah[i], bl[j]);
                    mma_bf16(c[i][j], al[i], bh[j]);
                }
        }
        __syncthreads();
    }
#undef ISSUE_CHUNK

    if (MODE == 1) {
#pragma unroll
        for (int i = 0; i < 4; i++) {
            const int row = m0 + warp_m * 64 + 16 * i + (lane >> 2);
#pragma unroll
            for (int j = 0; j < 4; j++) {
                const int col = n0 + warp_n * 32 + 8 * j + (lane & 3) * 2;
                const float b0 = bias[col], b1 = bias[col + 1];
                float2 v0 = make_float2(c[i][j][0] + b0, c[i][j][1] + b1);
                float2 v1 = make_float2(c[i][j][2] + b0, c[i][j][3] + b1);
                *(float2*)&outp[(size_t)row * DIM + col]       = v0;
                *(float2*)&outp[(size_t)(row + 8) * DIM + col] = v1;
            }
        }
        return;
    }

    // MODE 0: stage to smem so RoPE pairs (d, d+32) are in one thread
    float* st = (float*)sm;                 // 128 rows x 132 stride
#pragma unroll
    for (int i = 0; i < 4; i++) {
        const int rl = warp_m * 64 + 16 * i + (lane >> 2);
#pragma unroll
        for (int j = 0; j < 4; j++) {
            const int cl = warp_n * 32 + 8 * j + (lane & 3) * 2;
            st[rl * 132 + cl]           = c[i][j][0];
            st[rl * 132 + cl + 1]       = c[i][j][1];
            st[(rl + 8) * 132 + cl]     = c[i][j][2];
            st[(rl + 8) * 132 + cl + 1] = c[i][j][3];
        }
    }
    __syncthreads();

    const int comp = n0 >> 10;               // 0=q 1=k 2=v
    const int r  = tid >> 1;
    const int hl = tid & 1;
    const int token = m0 + r;
    const int s  = token & (SEQ - 1);
    const int bb = token >> 11;
    const int gh = ((n0 + hl * 64) >> 6) & (HEADS - 1);
    const float* brow = bias + n0 + hl * 64;
    const float* srow = st + r * 132 + hl * 64;

    float vals[64];
    if (comp < 2) {
#pragma unroll
        for (int d = 0; d < 32; d++) {
            float x1 = srow[d]      + brow[d];
            float x2 = srow[32 + d] + brow[32 + d];
            float cs = g_cos[s * 32 + d], sn = g_sin[s * 32 + d];
            vals[d]      = x1 * cs - x2 * sn;
            vals[d + 32] = x2 * cs + x1 * sn;
        }
        if (comp == 0) {
#pragma unroll
            for (int j = 0; j < 64; j++) vals[j] *= S0F;
        }
    } else {
#pragma unroll
        for (int j = 0; j < 64; j++) vals[j] = srow[j] + brow[j];
    }

    __nv_bfloat16* dh = (comp == 0) ? g_qhi : (comp == 1) ? g_khi : g_vhi;
    __nv_bfloat16* dl = (comp == 0) ? g_qlo : (comp == 1) ? g_klo : g_vlo;
    const size_t base = (((size_t)bb * HEADS + gh) * SEQ + s) * HDIM;
#pragma unroll
    for (int j2 = 0; j2 < 32; j2++) {
        float v0 = vals[2 * j2], v1 = vals[2 * j2 + 1];
        __nv_bfloat16 h0 = __float2bfloat16(v0), h1 = __float2bfloat16(v1);
        __nv_bfloat16 l0 = __float2bfloat16(v0 - __bfloat162float(h0));
        __nv_bfloat16 l1 = __float2bfloat16(v1 - __bfloat162float(h1));
        *(uint32_t*)(dh + base + 2 * j2) = bf2u(h0, h1);
        *(uint32_t*)(dl + base + 2 * j2) = bf2u(l0, l1);
    }
}

// ---------------------------------------------------------------------------
// MMA flash attention: grid (BH=32, QT=16), 128 threads (4 warps x 32 q-rows).
// 32-key tiles, split-bf16 QK^T and PV, online base-2 softmax, causal.
// smem: [0,16K) Qhi, [16K,32K) Qlo, [32K,64K) K/V double buffer
//       (per buf: KH +0, KL +4K, VH +8K, VL +12K)
// ---------------------------------------------------------------------------
#define ATTN_SMEM 65536

__global__ __launch_bounds__(128) void attn_mma_kernel() {
    extern __shared__ __align__(16) char sm[];
    const uint32_t smb = s2u32(sm);
    const int bh = blockIdx.x, qt = blockIdx.y;
    const int tid = threadIdx.x, wid = tid >> 5, lane = tid & 31;
    const int gid = lane >> 2, tq = lane & 3;

    const __nv_bfloat16* Qh = g_qhi + (size_t)bh * SEQ * HDIM;
    const __nv_bfloat16* Ql = g_qlo + (size_t)bh * SEQ * HDIM;
    const __nv_bfloat16* Kh = g_khi + (size_t)bh * SEQ * HDIM;
    const __nv_bfloat16* Kl = g_klo + (size_t)bh * SEQ * HDIM;
    const __nv_bfloat16* Vh = g_vhi + (size_t)bh * SEQ * HDIM;
    const __nv_bfloat16* Vl = g_vlo + (size_t)bh * SEQ * HDIM;

    // stage Q rows qt*128..+127 (hi at 0, lo at 16K)
    {
        const char* sh = (const char*)(Qh + (size_t)(qt * 128 + tid) * HDIM);
        const char* sl = (const char*)(Ql + (size_t)(qt * 128 + tid) * HDIM);
#pragma unroll
        for (int i = 0; i < 8; i++) {
            const uint32_t off = swz128(tid, i * 16);
            cpa16(smb + off, sh + i * 16);
            cpa16(smb + 16384 + off, sl + i * 16);
        }
    }
    CP_COMMIT();

    const int NT = 4 * qt + 4;

#define ISSUE_KV(t, b) do {                                                     \
    const int k0i = (t) * 32;                                                   \
    const uint32_t kb = smb + 32768 + (b) * 16384;                              \
    _Pragma("unroll")                                                           \
    for (int i = 0; i < 2; i++) {                                               \
        const int j = tid * 2 + i;                                              \
        const int rw = j >> 3, cbb = (j & 7) * 16;                              \
        const uint32_t off = swz128(rw, cbb);                                   \
        cpa16(kb + off,         (const char*)(Kh + (size_t)(k0i + rw) * HDIM) + cbb); \
        cpa16(kb + 4096 + off,  (const char*)(Kl + (size_t)(k0i + rw) * HDIM) + cbb); \
        cpa16(kb + 8192 + off,  (const char*)(Vh + (size_t)(k0i + rw) * HDIM) + cbb); \
        cpa16(kb + 12288 + off, (const char*)(Vl + (size_t)(k0i + rw) * HDIM) + cbb); \
    }                                                                           \
} while (0)

    ISSUE_KV(0, 0);
    CP_COMMIT();

    float c_o[2][8][4];
#pragma unroll
    for (int m = 0; m < 2; m++)
#pragma unroll
        for (int n = 0; n < 8; n++)
#pragma unroll
            for (int r = 0; r < 4; r++) c_o[m][n][r] = 0.0f;
    float m_s[2][2] = {{-1e30f, -1e30f}, {-1e30f, -1e30f}};
    float l_s[2][2] = {{0.0f, 0.0f}, {0.0f, 0.0f}};

    for (int t = 0; t < NT; t++) {
        const int buf = t & 1;
        if (t + 1 < NT) {
            ISSUE_KV(t + 1, buf ^ 1);
            CP_COMMIT();
            CP_WAIT(1);
        } else {
            CP_WAIT(0);
        }
        __syncthreads();

        const bool active = (t <= 4 * qt + wid);
        if (active) {
            const uint32_t kvb = smb + 32768 + buf * 16384;

            // ---- S = q . k^T (3-term split), 32 keys ----
            float c_s[2][4][4];
#pragma unroll
            for (int m = 0; m < 2; m++)
#pragma unroll
                for (int n = 0; n < 4; n++)
#pragma unroll
                    for (int r = 0; r < 4; r++) c_s[m][n][r] = 0.0f;

#pragma unroll
            for (int ks = 0; ks < 4; ks++) {
                uint32_t qa[2][4], qb[2][4];
#pragma unroll
                for (int m = 0; m < 2; m++) {
                    const uint32_t off = swz128(
                        wid * 32 + m * 16 + (lane & 7) + ((lane >> 3) & 1) * 8,
                        ks * 32 + ((lane >> 4) & 1) * 16);
                    ldsm_x4(qa[m], smb + off);
                    ldsm_x4(qb[m], smb + 16384 + off);
                }
                uint32_t kbf[4][2], klf[4][2];
#pragma unroll
                for (int jj = 0; jj < 2; jj++) {
                    const uint32_t off = swz128(
                        16 * jj + (lane & 7) + ((lane >> 4) & 1) * 8,
                        ks * 32 + ((lane >> 3) & 1) * 16);
                    uint32_t r[4];
                    ldsm_x4(r, kvb + off);
                    kbf[2 * jj][0] = r[0]; kbf[2 * jj][1] = r[1];
                    kbf[2 * jj + 1][0] = r[2]; kbf[2 * jj + 1][1] = r[3];
                    ldsm_x4(r, kvb + 4096 + off);
                    klf[2 * jj][0] = r[0]; klf[2 * jj][1] = r[1];
                    klf[2 * jj + 1][0] = r[2]; klf[2 * jj + 1][1] = r[3];
                }
#pragma unroll
                for (int m = 0; m < 2; m++)
#pragma unroll
                    for (int n = 0; n < 4; n++) {
                        mma_bf16(c_s[m][n], qa[m], kbf[n]);
                        mma_bf16(c_s[m][n], qa[m], klf[n]);
                        mma_bf16(c_s[m][n], qb[m], kbf[n]);
                    }
            }

            // ---- causal mask (exactly one edge tile per warp) ----
            if (t == 4 * qt + wid) {
                const int k0 = t * 32;
                const int rbase = qt * 128 + wid * 32;
#pragma unroll
                for (int m = 0; m < 2; m++) {
                    const int r0 = rbase + m * 16 + gid, r1 = r0 + 8;
#pragma unroll
                    for (int n = 0; n < 4; n++) {
                        const int key = k0 + 8 * n + 2 * tq;
                        if (key     > r0) c_s[m][n][0] = -1e30f;
                        if (key + 1 > r0) c_s[m][n][1] = -1e30f;
                        if (key     > r1) c_s[m][n][2] = -1e30f;
                        if (key + 1 > r1) c_s[m][n][3] = -1e30f;
                    }
                }
            }

            // ---- online softmax + P split-pack into A-frags ----
            uint32_t aph[2][2][4], apl[2][2][4];
#pragma unroll
            for (int m = 0; m < 2; m++) {
                float mx0 = -1e30f, mx1 = -1e30f;
#pragma unroll
                for (int n = 0; n < 4; n++) {
                    mx0 = fmaxf(mx0, fmaxf(c_s[m][n][0], c_s[m][n][1]));
                    mx1 = fmaxf(mx1, fmaxf(c_s[m][n][2], c_s[m][n][3]));
                }
                mx0 = fmaxf(mx0, __shfl_xor_sync(0xffffffffu, mx0, 1));
                mx0 = fmaxf(mx0, __shfl_xor_sync(0xffffffffu, mx0, 2));
                mx1 = fmaxf(mx1, __shfl_xor_sync(0xffffffffu, mx1, 1));
                mx1 = fmaxf(mx1, __shfl_xor_sync(0xffffffffu, mx1, 2));
                const float mn0 = fmaxf(m_s[m][0], mx0);
                const float mn1 = fmaxf(m_s[m][1], mx1);
                const float cr0 = ex2f(m_s[m][0] - mn0);
                const float cr1 = ex2f(m_s[m][1] - mn1);
                m_s[m][0] = mn0; m_s[m][1] = mn1;
                float s0 = 0.0f, s1 = 0.0f;
#pragma unroll
                for (int n = 0; n < 4; n++) {
                    const float p0 = ex2f(c_s[m][n][0] - mn0);
                    const float p1 = ex2f(c_s[m][n][1] - mn0);
                    const float p2 = ex2f(c_s[m][n][2] - mn1);
                    const float p3 = ex2f(c_s[m][n][3] - mn1);
                    s0 += p0 + p1; s1 += p2 + p3;
                    const __nv_bfloat16 h0 = __float2bfloat16(p0), h1 = __float2bfloat16(p1);
                    const __nv_bfloat16 h2 = __float2bfloat16(p2), h3 = __float2bfloat16(p3);
                    const __nv_bfloat16 e0 = __float2bfloat16(p0 - __bfloat162float(h0));
                    const __nv_bfloat16 e1 = __float2bfloat16(p1 - __bfloat162float(h1));
                    const __nv_bfloat16 e2 = __float2bfloat16(p2 - __bfloat162float(h2));
                    const __nv_bfloat16 e3 = __float2bfloat16(p3 - __bfloat162float(h3));
                    const int pk = n >> 1, half = (n & 1) * 2;
                    aph[m][pk][half]     = bf2u(h0, h1);
                    aph[m][pk][half + 1] = bf2u(h2, h3);
                    apl[m][pk][half]     = bf2u(e0, e1);
                    apl[m][pk][half + 1] = bf2u(e2, e3);
                }
                s0 += __shfl_xor_sync(0xffffffffu, s0, 1);
                s0 += __shfl_xor_sync(0xffffffffu, s0, 2);
                s1 += __shfl_xor_sync(0xffffffffu, s1, 1);
                s1 += __shfl_xor_sync(0xffffffffu, s1, 2);
                l_s[m][0] = l_s[m][0] * cr0 + s0;
                l_s[m][1] = l_s[m][1] * cr1 + s1;
#pragma unroll
                for (int n = 0; n < 8; n++) {
                    c_o[m][n][0] *= cr0; c_o[m][n][1] *= cr0;
                    c_o[m][n][2] *= cr1; c_o[m][n][3] *= cr1;
                }
            }

            // ---- O += P . V (3-term split), V frags via ldmatrix.trans ----
#pragma unroll
            for (int pk = 0; pk < 2; pk++) {
                uint32_t vhf[8][2], vlf[8][2];
#pragma unroll
                for (int jj = 0; jj < 4; jj++) {
                    const uint32_t off = swz128(
                        16 * pk + (lane & 7) + ((lane >> 3) & 1) * 8,
                        jj * 32 + ((lane >> 4) & 1) * 16);
                    uint32_t r[4];
                    ldsm_x4_t(r, kvb + 8192 + off);
                    vhf[2 * jj][0] = r[0]; vhf[2 * jj][1] = r[1];
                    vhf[2 * jj + 1][0] = r[2]; vhf[2 * jj + 1][1] = r[3];
                    ldsm_x4_t(r, kvb + 12288 + off);
                    vlf[2 * jj][0] = r[0]; vlf[2 * jj][1] = r[1];
                    vlf[2 * jj + 1][0] = r[2]; vlf[2 * jj + 1][1] = r[3];
                }
#pragma unroll
                for (int m = 0; m < 2; m++)
#pragma unroll
                    for (int n = 0; n < 8; n++) {
                        mma_bf16(c_o[m][n], aph[m][pk], vhf[n]);
                        mma_bf16(c_o[m][n], aph[m][pk], vlf[n]);
                        mma_bf16(c_o[m][n], apl[m][pk], vhf[n]);
                    }
            }
        }
        __syncthreads();
    }
#undef ISSUE_KV

    // ---- normalize + split-write to g_ahi/g_alo (B, S, D) ----
    const int bb = bh >> 4, hh = bh & (HEADS - 1);
#pragma unroll
    for (int m = 0; m < 2; m++) {
        const float i0 = 1.0f / l_s[m][0];
        const float i1 = 1.0f / l_s[m][1];
        const int r0 = qt * 128 + wid * 32 + m * 16 + gid;
        const int r1 = r0 + 8;
        const size_t a0 = ((size_t)bb * SEQ + r0) * DIM + hh * 64;
        const size_t a1 = ((size_t)bb * SEQ + r1) * DIM + hh * 64;
#pragma unroll
        for (int n = 0; n < 8; n++) {
            const int dcol = 8 * n + 2 * tq;
            const float v0 = c_o[m][n][0] * i0, v1 = c_o[m][n][1] * i0;
            const float v2 = c_o[m][n][2] * i1, v3 = c_o[m][n][3] * i1;
            const __nv_bfloat16 h0 = __float2bfloat16(v0), h1 = __float2bfloat16(v1);
            const __nv_bfloat16 h2 = __float2bfloat16(v2), h3 = __float2bfloat16(v3);
            const __nv_bfloat16 e0 = __float2bfloat16(v0 - __bfloat162float(h0));
            const __nv_bfloat16 e1 = __float2bfloat16(v1 - __bfloat162float(h1));
            const __nv_bfloat16 e2 = __float2bfloat16(v2 - __bfloat162float(h2));
            const __nv_bfloat16 e3 = __float2bfloat16(v3 - __bfloat162float(h3));
            *(uint32_t*)(g_ahi + a0 + dcol) = bf2u(h0, h1);
            *(uint32_t*)(g_alo + a0 + dcol) = bf2u(e0, e1);
            *(uint32_t*)(g_ahi + a1 + dcol) = bf2u(h2, h3);
            *(uint32_t*)(g_alo + a1 + dcol) = bf2u(e2, e3);
        }
    }
}

// ---------------------------------------------------------------------------
extern "C" void kernel_launch(void* const* d_in, const int* in_sizes, int n_in,
                              void* d_out, int out_size) {
    const float* query = 0;
    const float* W_qkv = 0;
    const float* b_qkv = 0;
    const float* W_out = 0;
    const float* b_out = 0;
    for (int i = 0; i < n_in; i++) {
        switch (in_sizes[i]) {
            case 4194304: query = (const float*)d_in[i]; break;
            case 3145728: W_qkv = (const float*)d_in[i]; break;
            case 3072:    b_qkv = (const float*)d_in[i]; break;
            case 1048576: W_out = (const float*)d_in[i]; break;
            case 1024:    b_out = (const float*)d_in[i]; break;
        }
    }
    float* out = (float*)d_out;

    cudaFuncSetAttribute(mma_gemm_kernel<0>, cudaFuncAttributeMaxDynamicSharedMemorySize, GSMEM);
    cudaFuncSetAttribute(mma_gemm_kernel<1>, cudaFuncAttributeMaxDynamicSharedMemorySize, GSMEM);
    cudaFuncSetAttribute(attn_mma_kernel, cudaFuncAttributeMaxDynamicSharedMemorySize, ATTN_SMEM);

    rope_table_kernel<<<(SEQ * 32 + 255) / 256, 256>>>();
    split_x_kernel<<<NTOK * DIM / 1024, 256>>>(query);
    transpose_split_kernel<<<dim3(QKV_N / 32, DIM / 32), dim3(32, 8)>>>(W_qkv, 0);
    transpose_split_kernel<<<dim3(DIM / 32, DIM / 32), dim3(32, 8)>>>(W_out, 1);

    mma_gemm_kernel<0><<<dim3(QKV_N / 128, NTOK / 128), 256, GSMEM>>>(b_qkv, nullptr);

    attn_mma_kernel<<<dim3(BATCH * HEADS, SEQ / 128), 128, ATTN_SMEM>>>();

    mma_gemm_kernel<1><<<dim3(DIM / 128, NTOK / 128), 256, GSMEM>>>(b_out, out);
}

// round 7
// speedup vs baseline: 3.2464x; 1.1726x over previous
#include <cuda_runtime.h>
#include <cuda_bf16.h>
#include <cuda_fp16.h>
#include <math.h>
#include <stdint.h>

#define BATCH 2
#define SEQ   2048
#define DIM   1024
#define HEADS 16
#define HDIM  64
#define NTOK  (BATCH*SEQ)          // 4096
#define QKV_N (3*DIM)              // 3072

typedef unsigned long long u64;

// 0.125 * log2(e): folds attention scale + base-2 softmax into q
#define S0F 0.18033688011112042f

// ---- helpers (all base-PTX, no 'a' features) --------------------------------
__device__ __forceinline__ uint32_t s2u32(const void* p) {
    uint32_t a;
    asm("{ .reg .u64 t; cvta.to.shared.u64 t, %1; cvt.u32.u64 %0, t; }" : "=r"(a) : "l"(p));
    return a;
}
__device__ __forceinline__ void ldsm_x4(uint32_t* r, uint32_t addr) {
    asm volatile("ldmatrix.sync.aligned.m8n8.x4.shared.b16 {%0,%1,%2,%3}, [%4];"
                 : "=r"(r[0]), "=r"(r[1]), "=r"(r[2]), "=r"(r[3]) : "r"(addr));
}
__device__ __forceinline__ void ldsm_x4_t(uint32_t* r, uint32_t addr) {
    asm volatile("ldmatrix.sync.aligned.m8n8.x4.trans.shared.b16 {%0,%1,%2,%3}, [%4];"
                 : "=r"(r[0]), "=r"(r[1]), "=r"(r[2]), "=r"(r[3]) : "r"(addr));
}
__device__ __forceinline__ void mma_bf16(float* c, const uint32_t* a, const uint32_t* b) {
    asm volatile(
        "mma.sync.aligned.m16n8k16.row.col.f32.bf16.bf16.f32 "
        "{%0,%1,%2,%3},{%4,%5,%6,%7},{%8,%9},{%0,%1,%2,%3};"
        : "+f"(c[0]), "+f"(c[1]), "+f"(c[2]), "+f"(c[3])
        : "r"(a[0]), "r"(a[1]), "r"(a[2]), "r"(a[3]), "r"(b[0]), "r"(b[1]));
}
__device__ __forceinline__ void mma_f16(float* c, const uint32_t* a, const uint32_t* b) {
    asm volatile(
        "mma.sync.aligned.m16n8k16.row.col.f32.f16.f16.f32 "
        "{%0,%1,%2,%3},{%4,%5,%6,%7},{%8,%9},{%0,%1,%2,%3};"
        : "+f"(c[0]), "+f"(c[1]), "+f"(c[2]), "+f"(c[3])
        : "r"(a[0]), "r"(a[1]), "r"(a[2]), "r"(a[3]), "r"(b[0]), "r"(b[1]));
}
__device__ __forceinline__ void cpa16(uint32_t dst, const void* src) {
    asm volatile("cp.async.cg.shared.global [%0], [%1], 16;" :: "r"(dst), "l"(src) : "memory");
}
#define CP_COMMIT() asm volatile("cp.async.commit_group;" ::: "memory")
#define CP_WAIT(n)  asm volatile("cp.async.wait_group %0;" :: "n"(n) : "memory")

__device__ __forceinline__ float ex2f(float x) {
    float r; asm("ex2.approx.f32 %0, %1;" : "=f"(r) : "f"(x)); return r;
}
__device__ __forceinline__ uint32_t bf2u(__nv_bfloat16 a, __nv_bfloat16 b) {
    __nv_bfloat162 t = __halves2bfloat162(a, b);
    return *(uint32_t*)&t;
}
__device__ __forceinline__ uint32_t hf2u(__half a, __half b) {
    __half2 t = __halves2half2(a, b);
    return *(uint32_t*)&t;
}

// SW64 swizzle for 64-byte rows (GEMM tiles, BK=32)
__device__ __forceinline__ uint32_t swzoff(int row, int kb) {
    return (uint32_t)(row * 64 + (kb ^ ((row & 6) << 3)));
}
// swizzle for 128-byte rows (attention tiles, 64 elems/row)
__device__ __forceinline__ uint32_t swz128(int row, int cb) {
    return (uint32_t)(row * 128 + (cb ^ ((row & 7) << 4)));
}

// ---- device scratch ----------------------------------------------------------
__device__ float g_cos[SEQ*32];
__device__ float g_sin[SEQ*32];
__device__ __half g_xhi[NTOK*DIM],  g_xlo[NTOK*DIM];      // split(X), fp16
__device__ __half g_wqT[QKV_N*DIM];                        // fp16(W_qkv^T) (N,K)
__device__ __half g_woT[DIM*DIM];                          // fp16(W_out^T) (N,K)
__device__ __nv_bfloat16 g_qhi[BATCH*HEADS*SEQ*HDIM], g_qlo[BATCH*HEADS*SEQ*HDIM];
__device__ __nv_bfloat16 g_khi[BATCH*HEADS*SEQ*HDIM], g_klo[BATCH*HEADS*SEQ*HDIM];
__device__ __nv_bfloat16 g_vhi[BATCH*HEADS*SEQ*HDIM], g_vlo[BATCH*HEADS*SEQ*HDIM];
__device__ __half g_ahi[NTOK*DIM],  g_alo[NTOK*DIM];      // split(attn out), fp16

// ---------------------------------------------------------------------------
// RoPE table (fp64 sincos for accuracy)
// ---------------------------------------------------------------------------
__global__ void rope_table_kernel() {
    int idx = blockIdx.x * blockDim.x + threadIdx.x;
    if (idx >= SEQ * 32) return;
    int s = idx >> 5;
    int j = idx & 31;
    double theta = (double)s * pow(10000.0, -(double)j / 32.0);
    double sc, cc;
    sincos(theta, &sc, &cc);
    g_cos[idx] = (float)cc;
    g_sin[idx] = (float)sc;
}

// ---------------------------------------------------------------------------
// Split X (fp32) -> fp16 hi/lo (exact 2-term: hi+lo == x to 2^-22)
// ---------------------------------------------------------------------------
__global__ __launch_bounds__(256) void split_x_kernel(const float* __restrict__ X) {
    int i = (blockIdx.x * 256 + threadIdx.x) * 4;
    float4 v = *(const float4*)(X + i);
    float a[4] = {v.x, v.y, v.z, v.w};
    __half h[4], l[4];
#pragma unroll
    for (int j = 0; j < 4; j++) {
        h[j] = __float2half(a[j]);
        l[j] = __float2half(a[j] - __half2float(h[j]));
    }
    *(uint32_t*)(g_xhi + i)     = hf2u(h[0], h[1]);
    *(uint32_t*)(g_xhi + i + 2) = hf2u(h[2], h[3]);
    *(uint32_t*)(g_xlo + i)     = hf2u(l[0], l[1]);
    *(uint32_t*)(g_xlo + i + 2) = hf2u(l[2], l[3]);
}

// ---------------------------------------------------------------------------
// Transpose weights: W (K=1024, N) row-major -> W^T (N, K=1024) single fp16
// ---------------------------------------------------------------------------
__global__ void transpose_f16_kernel(const float* __restrict__ W, int which) {
    __shared__ float t32[32][33];
    const int N = which ? DIM : QKV_N;
    __half* T = which ? g_woT : g_wqT;
    const int n0 = blockIdx.x * 32, k0 = blockIdx.y * 32;
    const int tx = threadIdx.x, ty = threadIdx.y;       // (32, 8)
#pragma unroll
    for (int i = 0; i < 4; i++)
        t32[ty + 8 * i][tx] = W[(size_t)(k0 + ty + 8 * i) * N + n0 + tx];
    __syncthreads();
#pragma unroll
    for (int i = 0; i < 4; i++) {
        float v = t32[tx][ty + 8 * i];
        T[(size_t)(n0 + ty + 8 * i) * DIM + k0 + tx] = __float2half(v);
    }
}

// ---------------------------------------------------------------------------
// Warp-MMA fp16 GEMM: D(fp32) = (Ah + Al) * B_fp16  (+bias, epilogue)
// CTA 128x128, 8 warps (2x4), warp tile 64x32, BK=32, 3-stage cp.async.
// MODE 0: X @ W_qkv + bias, RoPE, q scaled by S0F -> g_{q,k,v}{hi,lo} (bf16)
// MODE 1: attn @ W_out + bias -> outp (fp32)
// ---------------------------------------------------------------------------
#define OFF_AH  0
#define OFF_AL  8192
#define OFF_B   16384
#define BUF_SZ  24576
#define GSMEM   73728             // 3*BUF_SZ; also covers 128*132*4 staging

template<int MODE>
__global__ __launch_bounds__(256) void mma_gemm_kernel(const float* __restrict__ bias,
                                                       float* __restrict__ outp) {
    extern __shared__ __align__(16) char sm[];
    const uint32_t smb = s2u32(sm);
    const int tid  = threadIdx.x;
    const int wid  = tid >> 5;
    const int lane = tid & 31;
    const int warp_m = wid >> 2;
    const int warp_n = wid & 3;

    const int n0 = blockIdx.x * 128;
    const int m0 = blockIdx.y * 128;

    const __half* __restrict__ Ah = (MODE == 0) ? g_xhi : g_ahi;
    const __half* __restrict__ Al = (MODE == 0) ? g_xlo : g_alo;
    const __half* __restrict__ Bw = (MODE == 0) ? g_wqT : g_woT;

    float c[4][4][4];
#pragma unroll
    for (int i = 0; i < 4; i++)
#pragma unroll
        for (int j = 0; j < 4; j++)
#pragma unroll
            for (int r = 0; r < 4; r++) c[i][j][r] = 0.0f;

    const int ld_row = tid >> 2;
    const int ld_kb  = (tid & 3) * 16;

#define ISSUE_CHUNK(chunk, buf) do {                                           \
    const int k0e = (chunk) * 32;                                              \
    const uint32_t bb = smb + (buf) * BUF_SZ;                                  \
    _Pragma("unroll")                                                          \
    for (int m = 0; m < 2; m++) {                                              \
        const int row = ld_row + m * 64;                                       \
        const uint32_t so = swzoff(row, ld_kb);                                \
        cpa16(bb + OFF_AH + so, (const char*)(Ah + (size_t)(m0 + row) * DIM + k0e) + ld_kb); \
        cpa16(bb + OFF_AL + so, (const char*)(Al + (size_t)(m0 + row) * DIM + k0e) + ld_kb); \
        cpa16(bb + OFF_B  + so, (const char*)(Bw + (size_t)(n0 + row) * DIM + k0e) + ld_kb); \
    }                                                                          \
} while (0)

    ISSUE_CHUNK(0, 0);
    CP_COMMIT();
    ISSUE_CHUNK(1, 1);
    CP_COMMIT();

    for (int ch = 0; ch < 32; ch++) {
        if (ch + 2 < 32) CP_WAIT(1); else CP_WAIT(0);
        __syncthreads();
        if (ch + 2 < 32) {
            ISSUE_CHUNK(ch + 2, (ch + 2) % 3);
            CP_COMMIT();
        }

        const uint32_t bb = smb + (ch % 3) * BUF_SZ;
#pragma unroll
        for (int ks = 0; ks < 2; ks++) {
            uint32_t ah[4][4], al[4][4];
#pragma unroll
            for (int i = 0; i < 4; i++) {
                const int row = warp_m * 64 + 16 * i + (lane & 7) + ((lane >> 3) & 1) * 8;
                const int kb  = ks * 32 + (lane >> 4) * 16;
                const uint32_t so = swzoff(row, kb);
                ldsm_x4(ah[i], bb + OFF_AH + so);
                ldsm_x4(al[i], bb + OFF_AL + so);
            }
            uint32_t bf[4][2];
#pragma unroll
            for (int j2 = 0; j2 < 2; j2++) {
                const int row = warp_n * 32 + 16 * j2 + (lane & 7) + ((lane >> 4) & 1) * 8;
                const int kb  = ks * 32 + ((lane >> 3) & 1) * 16;
                const uint32_t so = swzoff(row, kb);
                uint32_t r[4];
                ldsm_x4(r, bb + OFF_B + so);
                bf[2 * j2][0] = r[0]; bf[2 * j2][1] = r[1];
                bf[2 * j2 + 1][0] = r[2]; bf[2 * j2 + 1][1] = r[3];
            }
#pragma unroll
            for (int i = 0; i < 4; i++)
#pragma unroll
                for (int j = 0; j < 4; j++) {
                    mma_f16(c[i][j], ah[i], bf[j]);
                    mma_f16(c[i][j], al[i], bf[j]);
                }
        }
        __syncthreads();
    }
#undef ISSUE_CHUNK

    if (MODE == 1) {
#pragma unroll
        for (int i = 0; i < 4; i++) {
            const int row = m0 + warp_m * 64 + 16 * i + (lane >> 2);
#pragma unroll
            for (int j = 0; j < 4; j++) {
                const int col = n0 + warp_n * 32 + 8 * j + (lane & 3) * 2;
                const float b0 = bias[col], b1 = bias[col + 1];
                float2 v0 = make_float2(c[i][j][0] + b0, c[i][j][1] + b1);
                float2 v1 = make_float2(c[i][j][2] + b0, c[i][j][3] + b1);
                *(float2*)&outp[(size_t)row * DIM + col]       = v0;
                *(float2*)&outp[(size_t)(row + 8) * DIM + col] = v1;
            }
        }
        return;
    }

    // MODE 0: stage to smem so RoPE pairs (d, d+32) are in one thread
    float* st = (float*)sm;                 // 128 rows x 132 stride
#pragma unroll
    for (int i = 0; i < 4; i++) {
        const int rl = warp_m * 64 + 16 * i + (lane >> 2);
#pragma unroll
        for (int j = 0; j < 4; j++) {
            const int cl = warp_n * 32 + 8 * j + (lane & 3) * 2;
            st[rl * 132 + cl]           = c[i][j][0];
            st[rl * 132 + cl + 1]       = c[i][j][1];
            st[(rl + 8) * 132 + cl]     = c[i][j][2];
            st[(rl + 8) * 132 + cl + 1] = c[i][j][3];
        }
    }
    __syncthreads();

    const int comp = n0 >> 10;               // 0=q 1=k 2=v
    const int r  = tid >> 1;
    const int hl = tid & 1;
    const int token = m0 + r;
    const int s  = token & (SEQ - 1);
    const int bb2 = token >> 11;
    const int gh = ((n0 + hl * 64) >> 6) & (HEADS - 1);
    const float* brow = bias + n0 + hl * 64;
    const float* srow = st + r * 132 + hl * 64;

    float vals[64];
    if (comp < 2) {
#pragma unroll
        for (int d = 0; d < 32; d++) {
            float x1 = srow[d]      + brow[d];
            float x2 = srow[32 + d] + brow[32 + d];
            float cs = g_cos[s * 32 + d], sn = g_sin[s * 32 + d];
            vals[d]      = x1 * cs - x2 * sn;
            vals[d + 32] = x2 * cs + x1 * sn;
        }
        if (comp == 0) {
#pragma unroll
            for (int j = 0; j < 64; j++) vals[j] *= S0F;
        }
    } else {
#pragma unroll
        for (int j = 0; j < 64; j++) vals[j] = srow[j] + brow[j];
    }

    __nv_bfloat16* dh = (comp == 0) ? g_qhi : (comp == 1) ? g_khi : g_vhi;
    __nv_bfloat16* dl = (comp == 0) ? g_qlo : (comp == 1) ? g_klo : g_vlo;
    const size_t base = (((size_t)bb2 * HEADS + gh) * SEQ + s) * HDIM;
#pragma unroll
    for (int j2 = 0; j2 < 32; j2++) {
        float v0 = vals[2 * j2], v1 = vals[2 * j2 + 1];
        __nv_bfloat16 h0 = __float2bfloat16(v0), h1 = __float2bfloat16(v1);
        __nv_bfloat16 l0 = __float2bfloat16(v0 - __bfloat162float(h0));
        __nv_bfloat16 l1 = __float2bfloat16(v1 - __bfloat162float(h1));
        *(uint32_t*)(dh + base + 2 * j2) = bf2u(h0, h1);
        *(uint32_t*)(dl + base + 2 * j2) = bf2u(l0, l1);
    }
}

// ---------------------------------------------------------------------------
// MMA flash attention: grid (BH=32, QT=16), 128 threads (4 warps x 32 q-rows).
// 32-key tiles, split-bf16 QK^T and PV (3-term), online base-2 softmax, causal.
// smem: [0,16K) Qhi, [16K,32K) Qlo, [32K,64K) K/V double buffer
// ---------------------------------------------------------------------------
#define ATTN_SMEM 65536

__global__ __launch_bounds__(128) void attn_mma_kernel() {
    extern __shared__ __align__(16) char sm[];
    const uint32_t smb = s2u32(sm);
    const int bh = blockIdx.x, qt = blockIdx.y;
    const int tid = threadIdx.x, wid = tid >> 5, lane = tid & 31;
    const int gid = lane >> 2, tq = lane & 3;

    const __nv_bfloat16* Qh = g_qhi + (size_t)bh * SEQ * HDIM;
    const __nv_bfloat16* Ql = g_qlo + (size_t)bh * SEQ * HDIM;
    const __nv_bfloat16* Kh = g_khi + (size_t)bh * SEQ * HDIM;
    const __nv_bfloat16* Kl = g_klo + (size_t)bh * SEQ * HDIM;
    const __nv_bfloat16* Vh = g_vhi + (size_t)bh * SEQ * HDIM;
    const __nv_bfloat16* Vl = g_vlo + (size_t)bh * SEQ * HDIM;

    {
        const char* sh = (const char*)(Qh + (size_t)(qt * 128 + tid) * HDIM);
        const char* sl = (const char*)(Ql + (size_t)(qt * 128 + tid) * HDIM);
#pragma unroll
        for (int i = 0; i < 8; i++) {
            const uint32_t off = swz128(tid, i * 16);
            cpa16(smb + off, sh + i * 16);
            cpa16(smb + 16384 + off, sl + i * 16);
        }
    }
    CP_COMMIT();

    const int NT = 4 * qt + 4;

#define ISSUE_KV(t, b) do {                                                     \
    const int k0i = (t) * 32;                                                   \
    const uint32_t kb = smb + 32768 + (b) * 16384;                              \
    _Pragma("unroll")                                                           \
    for (int i = 0; i < 2; i++) {                                               \
        const int j = tid * 2 + i;                                              \
        const int rw = j >> 3, cbb = (j & 7) * 16;                              \
        const uint32_t off = swz128(rw, cbb);                                   \
        cpa16(kb + off,         (const char*)(Kh + (size_t)(k0i + rw) * HDIM) + cbb); \
        cpa16(kb + 4096 + off,  (const char*)(Kl + (size_t)(k0i + rw) * HDIM) + cbb); \
        cpa16(kb + 8192 + off,  (const char*)(Vh + (size_t)(k0i + rw) * HDIM) + cbb); \
        cpa16(kb + 12288 + off, (const char*)(Vl + (size_t)(k0i + rw) * HDIM) + cbb); \
    }                                                                           \
} while (0)

    ISSUE_KV(0, 0);
    CP_COMMIT();

    float c_o[2][8][4];
#pragma unroll
    for (int m = 0; m < 2; m++)
#pragma unroll
        for (int n = 0; n < 8; n++)
#pragma unroll
            for (int r = 0; r < 4; r++) c_o[m][n][r] = 0.0f;
    float m_s[2][2] = {{-1e30f, -1e30f}, {-1e30f, -1e30f}};
    float l_s[2][2] = {{0.0f, 0.0f}, {0.0f, 0.0f}};

    for (int t = 0; t < NT; t++) {
        const int buf = t & 1;
        if (t + 1 < NT) {
            ISSUE_KV(t + 1, buf ^ 1);
            CP_COMMIT();
            CP_WAIT(1);
        } else {
            CP_WAIT(0);
        }
        __syncthreads();

        const bool active = (t <= 4 * qt + wid);
        if (active) {
            const uint32_t kvb = smb + 32768 + buf * 16384;

            float c_s[2][4][4];
#pragma unroll
            for (int m = 0; m < 2; m++)
#pragma unroll
                for (int n = 0; n < 4; n++)
#pragma unroll
                    for (int r = 0; r < 4; r++) c_s[m][n][r] = 0.0f;

#pragma unroll
            for (int ks = 0; ks < 4; ks++) {
                uint32_t qa[2][4], qb[2][4];
#pragma unroll
                for (int m = 0; m < 2; m++) {
                    const uint32_t off = swz128(
                        wid * 32 + m * 16 + (lane & 7) + ((lane >> 3) & 1) * 8,
                        ks * 32 + ((lane >> 4) & 1) * 16);
                    ldsm_x4(qa[m], smb + off);
                    ldsm_x4(qb[m], smb + 16384 + off);
                }
                uint32_t kbf[4][2], klf[4][2];
#pragma unroll
                for (int jj = 0; jj < 2; jj++) {
                    const uint32_t off = swz128(
                        16 * jj + (lane & 7) + ((lane >> 4) & 1) * 8,
                        ks * 32 + ((lane >> 3) & 1) * 16);
                    uint32_t r[4];
                    ldsm_x4(r, kvb + off);
                    kbf[2 * jj][0] = r[0]; kbf[2 * jj][1] = r[1];
                    kbf[2 * jj + 1][0] = r[2]; kbf[2 * jj + 1][1] = r[3];
                    ldsm_x4(r, kvb + 4096 + off);
                    klf[2 * jj][0] = r[0]; klf[2 * jj][1] = r[1];
                    klf[2 * jj + 1][0] = r[2]; klf[2 * jj + 1][1] = r[3];
                }
#pragma unroll
                for (int m = 0; m < 2; m++)
#pragma unroll
                    for (int n = 0; n < 4; n++) {
                        mma_bf16(c_s[m][n], qa[m], kbf[n]);
                        mma_bf16(c_s[m][n], qa[m], klf[n]);
                        mma_bf16(c_s[m][n], qb[m], kbf[n]);
                    }
            }

            if (t == 4 * qt + wid) {
                const int k0 = t * 32;
                const int rbase = qt * 128 + wid * 32;
#pragma unroll
                for (int m = 0; m < 2; m++) {
                    const int r0 = rbase + m * 16 + gid, r1 = r0 + 8;
#pragma unroll
                    for (int n = 0; n < 4; n++) {
                        const int key = k0 + 8 * n + 2 * tq;
                        if (key     > r0) c_s[m][n][0] = -1e30f;
                        if (key + 1 > r0) c_s[m][n][1] = -1e30f;
                        if (key     > r1) c_s[m][n][2] = -1e30f;
                        if (key + 1 > r1) c_s[m][n][3] = -1e30f;
                    }
                }
            }

            uint32_t aph[2][2][4], apl[2][2][4];
#pragma unroll
            for (int m = 0; m < 2; m++) {
                float mx0 = -1e30f, mx1 = -1e30f;
#pragma unroll
                for (int n = 0; n < 4; n++) {
                    mx0 = fmaxf(mx0, fmaxf(c_s[m][n][0], c_s[m][n][1]));
                    mx1 = fmaxf(mx1, fmaxf(c_s[m][n][2], c_s[m][n][3]));
                }
                mx0 = fmaxf(mx0, __shfl_xor_sync(0xffffffffu, mx0, 1));
                mx0 = fmaxf(mx0, __shfl_xor_sync(0xffffffffu, mx0, 2));
                mx1 = fmaxf(mx1, __shfl_xor_sync(0xffffffffu, mx1, 1));
                mx1 = fmaxf(mx1, __shfl_xor_sync(0xffffffffu, mx1, 2));
                const float mn0 = fmaxf(m_s[m][0], mx0);
                const float mn1 = fmaxf(m_s[m][1], mx1);
                const float cr0 = ex2f(m_s[m][0] - mn0);
                const float cr1 = ex2f(m_s[m][1] - mn1);
                m_s[m][0] = mn0; m_s[m][1] = mn1;
                float s0 = 0.0f, s1 = 0.0f;
#pragma unroll
                for (int n = 0; n < 4; n++) {
                    const float p0 = ex2f(c_s[m][n][0] - mn0);
                    const float p1 = ex2f(c_s[m][n][1] - mn0);
                    const float p2 = ex2f(c_s[m][n][2] - mn1);
                    const float p3 = ex2f(c_s[m][n][3] - mn1);
                    s0 += p0 + p1; s1 += p2 + p3;
                    const __nv_bfloat16 h0 = __float2bfloat16(p0), h1 = __float2bfloat16(p1);
                    const __nv_bfloat16 h2 = __float2bfloat16(p2), h3 = __float2bfloat16(p3);
                    const __nv_bfloat16 e0 = __float2bfloat16(p0 - __bfloat162float(h0));
                    const __nv_bfloat16 e1 = __float2bfloat16(p1 - __bfloat162float(h1));
                    const __nv_bfloat16 e2 = __float2bfloat16(p2 - __bfloat162float(h2));
                    const __nv_bfloat16 e3 = __float2bfloat16(p3 - __bfloat162float(h3));
                    const int pk = n >> 1, half = (n & 1) * 2;
                    aph[m][pk][half]     = bf2u(h0, h1);
                    aph[m][pk][half + 1] = bf2u(h2, h3);
                    apl[m][pk][half]     = bf2u(e0, e1);
                    apl[m][pk][half + 1] = bf2u(e2, e3);
                }
                s0 += __shfl_xor_sync(0xffffffffu, s0, 1);
                s0 += __shfl_xor_sync(0xffffffffu, s0, 2);
                s1 += __shfl_xor_sync(0xffffffffu, s1, 1);
                s1 += __shfl_xor_sync(0xffffffffu, s1, 2);
                l_s[m][0] = l_s[m][0] * cr0 + s0;
                l_s[m][1] = l_s[m][1] * cr1 + s1;
#pragma unroll
                for (int n = 0; n < 8; n++) {
                    c_o[m][n][0] *= cr0; c_o[m][n][1] *= cr0;
                    c_o[m][n][2] *= cr1; c_o[m][n][3] *= cr1;
                }
            }

#pragma unroll
            for (int pk = 0; pk < 2; pk++) {
                uint32_t vhf[8][2], vlf[8][2];
#pragma unroll
                for (int jj = 0; jj < 4; jj++) {
                    const uint32_t off = swz128(
                        16 * pk + (lane & 7) + ((lane >> 3) & 1) * 8,
                        jj * 32 + ((lane >> 4) & 1) * 16);
                    uint32_t r[4];
                    ldsm_x4_t(r, kvb + 8192 + off);
                    vhf[2 * jj][0] = r[0]; vhf[2 * jj][1] = r[1];
                    vhf[2 * jj + 1][0] = r[2]; vhf[2 * jj + 1][1] = r[3];
                    ldsm_x4_t(r, kvb + 12288 + off);
                    vlf[2 * jj][0] = r[0]; vlf[2 * jj][1] = r[1];
                    vlf[2 * jj + 1][0] = r[2]; vlf[2 * jj + 1][1] = r[3];
                }
#pragma unroll
                for (int m = 0; m < 2; m++)
#pragma unroll
                    for (int n = 0; n < 8; n++) {
                        mma_bf16(c_o[m][n], aph[m][pk], vhf[n]);
                        mma_bf16(c_o[m][n], aph[m][pk], vlf[n]);
                        mma_bf16(c_o[m][n], apl[m][pk], vhf[n]);
                    }
            }
        }
        __syncthreads();
    }
#undef ISSUE_KV

    // ---- normalize + fp16 split-write to g_ahi/g_alo (B, S, D) ----
    const int bb = bh >> 4, hh = bh & (HEADS - 1);
#pragma unroll
    for (int m = 0; m < 2; m++) {
        const float i0 = 1.0f / l_s[m][0];
        const float i1 = 1.0f / l_s[m][1];
        const int r0 = qt * 128 + wid * 32 + m * 16 + gid;
        const int r1 = r0 + 8;
        const size_t a0 = ((size_t)bb * SEQ + r0) * DIM + hh * 64;
        const size_t a1 = ((size_t)bb * SEQ + r1) * DIM + hh * 64;
#pragma unroll
        for (int n = 0; n < 8; n++) {
            const int dcol = 8 * n + 2 * tq;
            const float v0 = c_o[m][n][0] * i0, v1 = c_o[m][n][1] * i0;
            const float v2 = c_o[m][n][2] * i1, v3 = c_o[m][n][3] * i1;
            const __half h0 = __float2half(v0), h1 = __float2half(v1);
            const __half h2 = __float2half(v2), h3 = __float2half(v3);
            const __half e0 = __float2half(v0 - __half2float(h0));
            const __half e1 = __float2half(v1 - __half2float(h1));
            const __half e2 = __float2half(v2 - __half2float(h2));
            const __half e3 = __float2half(v3 - __half2float(h3));
            *(uint32_t*)(g_ahi + a0 + dcol) = hf2u(h0, h1);
            *(uint32_t*)(g_alo + a0 + dcol) = hf2u(e0, e1);
            *(uint32_t*)(g_ahi + a1 + dcol) = hf2u(h2, h3);
            *(uint32_t*)(g_alo + a1 + dcol) = hf2u(e2, e3);
        }
    }
}

// ---------------------------------------------------------------------------
extern "C" void kernel_launch(void* const* d_in, const int* in_sizes, int n_in,
                              void* d_out, int out_size) {
    const float* query = 0;
    const float* W_qkv = 0;
    const float* b_qkv = 0;
    const float* W_out = 0;
    const float* b_out = 0;
    for (int i = 0; i < n_in; i++) {
        switch (in_sizes[i]) {
            case 4194304: query = (const float*)d_in[i]; break;
            case 3145728: W_qkv = (const float*)d_in[i]; break;
            case 3072:    b_qkv = (const float*)d_in[i]; break;
            case 1048576: W_out = (const float*)d_in[i]; break;
            case 1024:    b_out = (const float*)d_in[i]; break;
        }
    }
    float* out = (float*)d_out;

    cudaFuncSetAttribute(mma_gemm_kernel<0>, cudaFuncAttributeMaxDynamicSharedMemorySize, GSMEM);
    cudaFuncSetAttribute(mma_gemm_kernel<1>, cudaFuncAttributeMaxDynamicSharedMemorySize, GSMEM);
    cudaFuncSetAttribute(attn_mma_kernel, cudaFuncAttributeMaxDynamicSharedMemorySize, ATTN_SMEM);

    rope_table_kernel<<<(SEQ * 32 + 255) / 256, 256>>>();
    split_x_kernel<<<NTOK * DIM / 1024, 256>>>(query);
    transpose_f16_kernel<<<dim3(QKV_N / 32, DIM / 32), dim3(32, 8)>>>(W_qkv, 0);
    transpose_f16_kernel<<<dim3(DIM / 32, DIM / 32), dim3(32, 8)>>>(W_out, 1);

    mma_gemm_kernel<0><<<dim3(QKV_N / 128, NTOK / 128), 256, GSMEM>>>(b_qkv, nullptr);

    attn_mma_kernel<<<dim3(BATCH * HEADS, SEQ / 128), 128, ATTN_SMEM>>>();

    mma_gemm_kernel<1><<<dim3(DIM / 128, NTOK / 128), 256, GSMEM>>>(b_out, out);
}

// round 8
// speedup vs baseline: 4.1205x; 1.2692x over previous
#include <cuda_runtime.h>
#include <cuda_bf16.h>
#include <cuda_fp16.h>
#include <math.h>
#include <stdint.h>

#define BATCH 2
#define SEQ   2048
#define DIM   1024
#define HEADS 16
#define HDIM  64
#define NTOK  (BATCH*SEQ)          // 4096
#define QKV_N (3*DIM)              // 3072

typedef unsigned long long u64;

// 0.125 * log2(e): folds attention scale + base-2 softmax into q
#define S0F 0.18033688011112042f

// ---- helpers (all base-PTX, no 'a' features) --------------------------------
__device__ __forceinline__ uint32_t s2u32(const void* p) {
    uint32_t a;
    asm("{ .reg .u64 t; cvta.to.shared.u64 t, %1; cvt.u32.u64 %0, t; }" : "=r"(a) : "l"(p));
    return a;
}
__device__ __forceinline__ void ldsm_x4(uint32_t* r, uint32_t addr) {
    asm volatile("ldmatrix.sync.aligned.m8n8.x4.shared.b16 {%0,%1,%2,%3}, [%4];"
                 : "=r"(r[0]), "=r"(r[1]), "=r"(r[2]), "=r"(r[3]) : "r"(addr));
}
__device__ __forceinline__ void ldsm_x4_t(uint32_t* r, uint32_t addr) {
    asm volatile("ldmatrix.sync.aligned.m8n8.x4.trans.shared.b16 {%0,%1,%2,%3}, [%4];"
                 : "=r"(r[0]), "=r"(r[1]), "=r"(r[2]), "=r"(r[3]) : "r"(addr));
}
__device__ __forceinline__ void mma_f16(float* c, const uint32_t* a, const uint32_t* b) {
    asm volatile(
        "mma.sync.aligned.m16n8k16.row.col.f32.f16.f16.f32 "
        "{%0,%1,%2,%3},{%4,%5,%6,%7},{%8,%9},{%0,%1,%2,%3};"
        : "+f"(c[0]), "+f"(c[1]), "+f"(c[2]), "+f"(c[3])
        : "r"(a[0]), "r"(a[1]), "r"(a[2]), "r"(a[3]), "r"(b[0]), "r"(b[1]));
}
__device__ __forceinline__ void cpa16(uint32_t dst, const void* src) {
    asm volatile("cp.async.cg.shared.global [%0], [%1], 16;" :: "r"(dst), "l"(src) : "memory");
}
#define CP_COMMIT() asm volatile("cp.async.commit_group;" ::: "memory")
#define CP_WAIT(n)  asm volatile("cp.async.wait_group %0;" :: "n"(n) : "memory")

__device__ __forceinline__ float ex2f(float x) {
    float r; asm("ex2.approx.f32 %0, %1;" : "=f"(r) : "f"(x)); return r;
}
__device__ __forceinline__ uint32_t hf2u(__half a, __half b) {
    __half2 t = __halves2half2(a, b);
    return *(uint32_t*)&t;
}

// SW64 swizzle for 64-byte rows (GEMM tiles, BK=32)
__device__ __forceinline__ uint32_t swzoff(int row, int kb) {
    return (uint32_t)(row * 64 + (kb ^ ((row & 6) << 3)));
}
// swizzle for 128-byte rows (attention tiles, 64 elems/row)
__device__ __forceinline__ uint32_t swz128(int row, int cb) {
    return (uint32_t)(row * 128 + (cb ^ ((row & 7) << 4)));
}

// ---- device scratch ----------------------------------------------------------
__device__ float g_cos[SEQ*32];
__device__ float g_sin[SEQ*32];
__device__ __half g_xhi[NTOK*DIM],  g_xlo[NTOK*DIM];      // split(X), fp16
__device__ __half g_wqT[QKV_N*DIM];                        // fp16(W_qkv^T) (N,K)
__device__ __half g_woT[DIM*DIM];                          // fp16(W_out^T) (N,K)
__device__ __half g_qhi[BATCH*HEADS*SEQ*HDIM], g_qlo[BATCH*HEADS*SEQ*HDIM];
__device__ __half g_kf[BATCH*HEADS*SEQ*HDIM];              // single fp16 K
__device__ __half g_vf[BATCH*HEADS*SEQ*HDIM];              // single fp16 V
__device__ __half g_ahi[NTOK*DIM],  g_alo[NTOK*DIM];      // split(attn out), fp16

// ---------------------------------------------------------------------------
// RoPE table (fp64 sincos for accuracy)
// ---------------------------------------------------------------------------
__global__ void rope_table_kernel() {
    int idx = blockIdx.x * blockDim.x + threadIdx.x;
    if (idx >= SEQ * 32) return;
    int s = idx >> 5;
    int j = idx & 31;
    double theta = (double)s * pow(10000.0, -(double)j / 32.0);
    double sc, cc;
    sincos(theta, &sc, &cc);
    g_cos[idx] = (float)cc;
    g_sin[idx] = (float)sc;
}

// ---------------------------------------------------------------------------
// Split X (fp32) -> fp16 hi/lo (exact 2-term)
// ---------------------------------------------------------------------------
__global__ __launch_bounds__(256) void split_x_kernel(const float* __restrict__ X) {
    int i = (blockIdx.x * 256 + threadIdx.x) * 4;
    float4 v = *(const float4*)(X + i);
    float a[4] = {v.x, v.y, v.z, v.w};
    __half h[4], l[4];
#pragma unroll
    for (int j = 0; j < 4; j++) {
        h[j] = __float2half(a[j]);
        l[j] = __float2half(a[j] - __half2float(h[j]));
    }
    *(uint32_t*)(g_xhi + i)     = hf2u(h[0], h[1]);
    *(uint32_t*)(g_xhi + i + 2) = hf2u(h[2], h[3]);
    *(uint32_t*)(g_xlo + i)     = hf2u(l[0], l[1]);
    *(uint32_t*)(g_xlo + i + 2) = hf2u(l[2], l[3]);
}

// ---------------------------------------------------------------------------
// Transpose weights: W (K=1024, N) row-major -> W^T (N, K=1024) single fp16
// ---------------------------------------------------------------------------
__global__ void transpose_f16_kernel(const float* __restrict__ W, int which) {
    __shared__ float t32[32][33];
    const int N = which ? DIM : QKV_N;
    __half* T = which ? g_woT : g_wqT;
    const int n0 = blockIdx.x * 32, k0 = blockIdx.y * 32;
    const int tx = threadIdx.x, ty = threadIdx.y;       // (32, 8)
#pragma unroll
    for (int i = 0; i < 4; i++)
        t32[ty + 8 * i][tx] = W[(size_t)(k0 + ty + 8 * i) * N + n0 + tx];
    __syncthreads();
#pragma unroll
    for (int i = 0; i < 4; i++) {
        float v = t32[tx][ty + 8 * i];
        T[(size_t)(n0 + ty + 8 * i) * DIM + k0 + tx] = __float2half(v);
    }
}

// ---------------------------------------------------------------------------
// Warp-MMA fp16 GEMM: D(fp32) = (Ah + Al) * B_fp16  (+bias, epilogue)
// CTA 128x128, 8 warps (2x4), warp tile 64x32, BK=32, 4-stage cp.async,
// one __syncthreads per chunk, 2 CTAs/SM.
// MODE 0: X @ W_qkv + bias, RoPE -> q split fp16 (scaled), k/v single fp16
// MODE 1: attn @ W_out + bias -> outp (fp32)
// ---------------------------------------------------------------------------
#define OFF_AH  0
#define OFF_AL  8192
#define OFF_B   16384
#define BUF_SZ  24576
#define GSMEM   98304             // 4*BUF_SZ; also covers 128*132*4 staging

template<int MODE>
__global__ __launch_bounds__(256, 2) void mma_gemm_kernel(const float* __restrict__ bias,
                                                          float* __restrict__ outp) {
    extern __shared__ __align__(16) char sm[];
    const uint32_t smb = s2u32(sm);
    const int tid  = threadIdx.x;
    const int wid  = tid >> 5;
    const int lane = tid & 31;
    const int warp_m = wid >> 2;
    const int warp_n = wid & 3;

    const int n0 = blockIdx.x * 128;
    const int m0 = blockIdx.y * 128;

    const __half* __restrict__ Ah = (MODE == 0) ? g_xhi : g_ahi;
    const __half* __restrict__ Al = (MODE == 0) ? g_xlo : g_alo;
    const __half* __restrict__ Bw = (MODE == 0) ? g_wqT : g_woT;

    float c[4][4][4];
#pragma unroll
    for (int i = 0; i < 4; i++)
#pragma unroll
        for (int j = 0; j < 4; j++)
#pragma unroll
            for (int r = 0; r < 4; r++) c[i][j][r] = 0.0f;

    const int ld_row = tid >> 2;
    const int ld_kb  = (tid & 3) * 16;

#define ISSUE_CHUNK(chunk, buf) do {                                           \
    const int k0e = (chunk) * 32;                                              \
    const uint32_t bb = smb + (buf) * BUF_SZ;                                  \
    _Pragma("unroll")                                                          \
    for (int m = 0; m < 2; m++) {                                              \
        const int row = ld_row + m * 64;                                       \
        const uint32_t so = swzoff(row, ld_kb);                                \
        cpa16(bb + OFF_AH + so, (const char*)(Ah + (size_t)(m0 + row) * DIM + k0e) + ld_kb); \
        cpa16(bb + OFF_AL + so, (const char*)(Al + (size_t)(m0 + row) * DIM + k0e) + ld_kb); \
        cpa16(bb + OFF_B  + so, (const char*)(Bw + (size_t)(n0 + row) * DIM + k0e) + ld_kb); \
    }                                                                          \
} while (0)

    ISSUE_CHUNK(0, 0); CP_COMMIT();
    ISSUE_CHUNK(1, 1); CP_COMMIT();
    ISSUE_CHUNK(2, 2); CP_COMMIT();

    for (int ch = 0; ch < 32; ch++) {
        if (ch <= 29) { CP_WAIT(2); }
        else if (ch == 30) { CP_WAIT(1); }
        else { CP_WAIT(0); }
        __syncthreads();
        if (ch + 3 < 32) {
            ISSUE_CHUNK(ch + 3, (ch + 3) & 3);
            CP_COMMIT();
        }

        const uint32_t bb = smb + (ch & 3) * BUF_SZ;
#pragma unroll
        for (int ks = 0; ks < 2; ks++) {
            uint32_t ah[4][4], al[4][4];
#pragma unroll
            for (int i = 0; i < 4; i++) {
                const int row = warp_m * 64 + 16 * i + (lane & 7) + ((lane >> 3) & 1) * 8;
                const int kb  = ks * 32 + (lane >> 4) * 16;
                const uint32_t so = swzoff(row, kb);
                ldsm_x4(ah[i], bb + OFF_AH + so);
                ldsm_x4(al[i], bb + OFF_AL + so);
            }
            uint32_t bf[4][2];
#pragma unroll
            for (int j2 = 0; j2 < 2; j2++) {
                const int row = warp_n * 32 + 16 * j2 + (lane & 7) + ((lane >> 4) & 1) * 8;
                const int kb  = ks * 32 + ((lane >> 3) & 1) * 16;
                const uint32_t so = swzoff(row, kb);
                uint32_t r[4];
                ldsm_x4(r, bb + OFF_B + so);
                bf[2 * j2][0] = r[0]; bf[2 * j2][1] = r[1];
                bf[2 * j2 + 1][0] = r[2]; bf[2 * j2 + 1][1] = r[3];
            }
#pragma unroll
            for (int i = 0; i < 4; i++)
#pragma unroll
                for (int j = 0; j < 4; j++) {
                    mma_f16(c[i][j], ah[i], bf[j]);
                    mma_f16(c[i][j], al[i], bf[j]);
                }
        }
    }
#undef ISSUE_CHUNK

    if (MODE == 1) {
#pragma unroll
        for (int i = 0; i < 4; i++) {
            const int row = m0 + warp_m * 64 + 16 * i + (lane >> 2);
#pragma unroll
            for (int j = 0; j < 4; j++) {
                const int col = n0 + warp_n * 32 + 8 * j + (lane & 3) * 2;
                const float b0 = bias[col], b1 = bias[col + 1];
                float2 v0 = make_float2(c[i][j][0] + b0, c[i][j][1] + b1);
                float2 v1 = make_float2(c[i][j][2] + b0, c[i][j][3] + b1);
                *(float2*)&outp[(size_t)row * DIM + col]       = v0;
                *(float2*)&outp[(size_t)(row + 8) * DIM + col] = v1;
            }
        }
        return;
    }

    // MODE 0: stage to smem so RoPE pairs (d, d+32) are in one thread
    __syncthreads();
    float* st = (float*)sm;                 // 128 rows x 132 stride
#pragma unroll
    for (int i = 0; i < 4; i++) {
        const int rl = warp_m * 64 + 16 * i + (lane >> 2);
#pragma unroll
        for (int j = 0; j < 4; j++) {
            const int cl = warp_n * 32 + 8 * j + (lane & 3) * 2;
            st[rl * 132 + cl]           = c[i][j][0];
            st[rl * 132 + cl + 1]       = c[i][j][1];
            st[(rl + 8) * 132 + cl]     = c[i][j][2];
            st[(rl + 8) * 132 + cl + 1] = c[i][j][3];
        }
    }
    __syncthreads();

    const int comp = n0 >> 10;               // 0=q 1=k 2=v
    const int r  = tid >> 1;
    const int hl = tid & 1;
    const int token = m0 + r;
    const int s  = token & (SEQ - 1);
    const int bb2 = token >> 11;
    const int gh = ((n0 + hl * 64) >> 6) & (HEADS - 1);
    const float* brow = bias + n0 + hl * 64;
    const float* srow = st + r * 132 + hl * 64;

    float vals[64];
    if (comp < 2) {
#pragma unroll
        for (int d = 0; d < 32; d++) {
            float x1 = srow[d]      + brow[d];
            float x2 = srow[32 + d] + brow[32 + d];
            float cs = g_cos[s * 32 + d], sn = g_sin[s * 32 + d];
            vals[d]      = x1 * cs - x2 * sn;
            vals[d + 32] = x2 * cs + x1 * sn;
        }
        if (comp == 0) {
#pragma unroll
            for (int j = 0; j < 64; j++) vals[j] *= S0F;
        }
    } else {
#pragma unroll
        for (int j = 0; j < 64; j++) vals[j] = srow[j] + brow[j];
    }

    const size_t base = (((size_t)bb2 * HEADS + gh) * SEQ + s) * HDIM;
    if (comp == 0) {
#pragma unroll
        for (int j2 = 0; j2 < 32; j2++) {
            float v0 = vals[2 * j2], v1 = vals[2 * j2 + 1];
            __half h0 = __float2half(v0), h1 = __float2half(v1);
            __half l0 = __float2half(v0 - __half2float(h0));
            __half l1 = __float2half(v1 - __half2float(h1));
            *(uint32_t*)(g_qhi + base + 2 * j2) = hf2u(h0, h1);
            *(uint32_t*)(g_qlo + base + 2 * j2) = hf2u(l0, l1);
        }
    } else {
        __half* df = (comp == 1) ? g_kf : g_vf;
#pragma unroll
        for (int j2 = 0; j2 < 32; j2++)
            *(uint32_t*)(df + base + 2 * j2) =
                hf2u(__float2half(vals[2 * j2]), __float2half(vals[2 * j2 + 1]));
    }
}

// ---------------------------------------------------------------------------
// MMA flash attention: grid (BH=32, QT=16), 128 threads (4 warps x 32 q-rows).
// 32-key tiles; QK = (qh+ql) x k_fp16; PV = (ph+pl) x v_fp16; base-2 softmax.
// smem: [0,16K) Qhi, [16K,32K) Qlo, bufs at 32K+b*8K: K +0, V +4096.
// ---------------------------------------------------------------------------
#define ATTN_SMEM 49152

__global__ __launch_bounds__(128) void attn_mma_kernel() {
    extern __shared__ __align__(16) char sm[];
    const uint32_t smb = s2u32(sm);
    const int bh = blockIdx.x, qt = blockIdx.y;
    const int tid = threadIdx.x, wid = tid >> 5, lane = tid & 31;
    const int gid = lane >> 2, tq = lane & 3;

    const __half* Qh = g_qhi + (size_t)bh * SEQ * HDIM;
    const __half* Ql = g_qlo + (size_t)bh * SEQ * HDIM;
    const __half* Kf = g_kf  + (size_t)bh * SEQ * HDIM;
    const __half* Vf = g_vf  + (size_t)bh * SEQ * HDIM;

    {
        const char* sh = (const char*)(Qh + (size_t)(qt * 128 + tid) * HDIM);
        const char* sl = (const char*)(Ql + (size_t)(qt * 128 + tid) * HDIM);
#pragma unroll
        for (int i = 0; i < 8; i++) {
            const uint32_t off = swz128(tid, i * 16);
            cpa16(smb + off, sh + i * 16);
            cpa16(smb + 16384 + off, sl + i * 16);
        }
    }
    CP_COMMIT();

    const int NT = 4 * qt + 4;

#define ISSUE_KV(t, b) do {                                                     \
    const int k0i = (t) * 32;                                                   \
    const uint32_t kb = smb + 32768 + (b) * 8192;                               \
    _Pragma("unroll")                                                           \
    for (int i = 0; i < 2; i++) {                                               \
        const int j = tid * 2 + i;                                              \
        const int rw = j >> 3, cbb = (j & 7) * 16;                              \
        const uint32_t off = swz128(rw, cbb);                                   \
        cpa16(kb + off,        (const char*)(Kf + (size_t)(k0i + rw) * HDIM) + cbb); \
        cpa16(kb + 4096 + off, (const char*)(Vf + (size_t)(k0i + rw) * HDIM) + cbb); \
    }                                                                           \
} while (0)

    ISSUE_KV(0, 0);
    CP_COMMIT();

    float c_o[2][8][4];
#pragma unroll
    for (int m = 0; m < 2; m++)
#pragma unroll
        for (int n = 0; n < 8; n++)
#pragma unroll
            for (int r = 0; r < 4; r++) c_o[m][n][r] = 0.0f;
    float m_s[2][2] = {{-1e30f, -1e30f}, {-1e30f, -1e30f}};
    float l_s[2][2] = {{0.0f, 0.0f}, {0.0f, 0.0f}};

    for (int t = 0; t < NT; t++) {
        const int buf = t & 1;
        CP_WAIT(0);
        __syncthreads();
        if (t + 1 < NT) {
            ISSUE_KV(t + 1, buf ^ 1);
            CP_COMMIT();
        }

        const bool active = (t <= 4 * qt + wid);
        if (active) {
            const uint32_t kvb = smb + 32768 + buf * 8192;

            float c_s[2][4][4];
#pragma unroll
            for (int m = 0; m < 2; m++)
#pragma unroll
                for (int n = 0; n < 4; n++)
#pragma unroll
                    for (int r = 0; r < 4; r++) c_s[m][n][r] = 0.0f;

#pragma unroll
            for (int ks = 0; ks < 4; ks++) {
                uint32_t qa[2][4], qb[2][4];
#pragma unroll
                for (int m = 0; m < 2; m++) {
                    const uint32_t off = swz128(
                        wid * 32 + m * 16 + (lane & 7) + ((lane >> 3) & 1) * 8,
                        ks * 32 + ((lane >> 4) & 1) * 16);
                    ldsm_x4(qa[m], smb + off);
                    ldsm_x4(qb[m], smb + 16384 + off);
                }
                uint32_t kf[4][2];
#pragma unroll
                for (int jj = 0; jj < 2; jj++) {
                    const uint32_t off = swz128(
                        16 * jj + (lane & 7) + ((lane >> 4) & 1) * 8,
                        ks * 32 + ((lane >> 3) & 1) * 16);
                    uint32_t r[4];
                    ldsm_x4(r, kvb + off);
                    kf[2 * jj][0] = r[0]; kf[2 * jj][1] = r[1];
                    kf[2 * jj + 1][0] = r[2]; kf[2 * jj + 1][1] = r[3];
                }
#pragma unroll
                for (int m = 0; m < 2; m++)
#pragma unroll
                    for (int n = 0; n < 4; n++) {
                        mma_f16(c_s[m][n], qa[m], kf[n]);
                        mma_f16(c_s[m][n], qb[m], kf[n]);
                    }
            }

            if (t == 4 * qt + wid) {
                const int k0 = t * 32;
                const int rbase = qt * 128 + wid * 32;
#pragma unroll
                for (int m = 0; m < 2; m++) {
                    const int r0 = rbase + m * 16 + gid, r1 = r0 + 8;
#pragma unroll
                    for (int n = 0; n < 4; n++) {
                        const int key = k0 + 8 * n + 2 * tq;
                        if (key     > r0) c_s[m][n][0] = -1e30f;
                        if (key + 1 > r0) c_s[m][n][1] = -1e30f;
                        if (key     > r1) c_s[m][n][2] = -1e30f;
                        if (key + 1 > r1) c_s[m][n][3] = -1e30f;
                    }
                }
            }

            uint32_t aph[2][2][4], apl[2][2][4];
#pragma unroll
            for (int m = 0; m < 2; m++) {
                float mx0 = -1e30f, mx1 = -1e30f;
#pragma unroll
                for (int n = 0; n < 4; n++) {
                    mx0 = fmaxf(mx0, fmaxf(c_s[m][n][0], c_s[m][n][1]));
                    mx1 = fmaxf(mx1, fmaxf(c_s[m][n][2], c_s[m][n][3]));
                }
                mx0 = fmaxf(mx0, __shfl_xor_sync(0xffffffffu, mx0, 1));
                mx0 = fmaxf(mx0, __shfl_xor_sync(0xffffffffu, mx0, 2));
                mx1 = fmaxf(mx1, __shfl_xor_sync(0xffffffffu, mx1, 1));
                mx1 = fmaxf(mx1, __shfl_xor_sync(0xffffffffu, mx1, 2));
                const float mn0 = fmaxf(m_s[m][0], mx0);
                const float mn1 = fmaxf(m_s[m][1], mx1);
                const float cr0 = ex2f(m_s[m][0] - mn0);
                const float cr1 = ex2f(m_s[m][1] - mn1);
                m_s[m][0] = mn0; m_s[m][1] = mn1;
                float s0 = 0.0f, s1 = 0.0f;
#pragma unroll
                for (int n = 0; n < 4; n++) {
                    const float p0 = ex2f(c_s[m][n][0] - mn0);
                    const float p1 = ex2f(c_s[m][n][1] - mn0);
                    const float p2 = ex2f(c_s[m][n][2] - mn1);
                    const float p3 = ex2f(c_s[m][n][3] - mn1);
                    s0 += p0 + p1; s1 += p2 + p3;
                    const __half h0 = __float2half(p0), h1 = __float2half(p1);
                    const __half h2 = __float2half(p2), h3 = __float2half(p3);
                    const __half e0 = __float2half(p0 - __half2float(h0));
                    const __half e1 = __float2half(p1 - __half2float(h1));
                    const __half e2 = __float2half(p2 - __half2float(h2));
                    const __half e3 = __float2half(p3 - __half2float(h3));
                    const int pk = n >> 1, half = (n & 1) * 2;
                    aph[m][pk][half]     = hf2u(h0, h1);
                    aph[m][pk][half + 1] = hf2u(h2, h3);
                    apl[m][pk][half]     = hf2u(e0, e1);
                    apl[m][pk][half + 1] = hf2u(e2, e3);
                }
                s0 += __shfl_xor_sync(0xffffffffu, s0, 1);
                s0 += __shfl_xor_sync(0xffffffffu, s0, 2);
                s1 += __shfl_xor_sync(0xffffffffu, s1, 1);
                s1 += __shfl_xor_sync(0xffffffffu, s1, 2);
                l_s[m][0] = l_s[m][0] * cr0 + s0;
                l_s[m][1] = l_s[m][1] * cr1 + s1;
#pragma unroll
                for (int n = 0; n < 8; n++) {
                    c_o[m][n][0] *= cr0; c_o[m][n][1] *= cr0;
                    c_o[m][n][2] *= cr1; c_o[m][n][3] *= cr1;
                }
            }

#pragma unroll
            for (int pk = 0; pk < 2; pk++) {
                uint32_t vf[8][2];
#pragma unroll
                for (int jj = 0; jj < 4; jj++) {
                    const uint32_t off = swz128(
                        16 * pk + (lane & 7) + ((lane >> 3) & 1) * 8,
                        jj * 32 + ((lane >> 4) & 1) * 16);
                    uint32_t r[4];
                    ldsm_x4_t(r, kvb + 4096 + off);
                    vf[2 * jj][0] = r[0]; vf[2 * jj][1] = r[1];
                    vf[2 * jj + 1][0] = r[2]; vf[2 * jj + 1][1] = r[3];
                }
#pragma unroll
                for (int m = 0; m < 2; m++)
#pragma unroll
                    for (int n = 0; n < 8; n++) {
                        mma_f16(c_o[m][n], aph[m][pk], vf[n]);
                        mma_f16(c_o[m][n], apl[m][pk], vf[n]);
                    }
            }
        }
    }
#undef ISSUE_KV

    // ---- normalize + fp16 split-write to g_ahi/g_alo (B, S, D) ----
    const int bb = bh >> 4, hh = bh & (HEADS - 1);
#pragma unroll
    for (int m = 0; m < 2; m++) {
        const float i0 = 1.0f / l_s[m][0];
        const float i1 = 1.0f / l_s[m][1];
        const int r0 = qt * 128 + wid * 32 + m * 16 + gid;
        const int r1 = r0 + 8;
        const size_t a0 = ((size_t)bb * SEQ + r0) * DIM + hh * 64;
        const size_t a1 = ((size_t)bb * SEQ + r1) * DIM + hh * 64;
#pragma unroll
        for (int n = 0; n < 8; n++) {
            const int dcol = 8 * n + 2 * tq;
            const float v0 = c_o[m][n][0] * i0, v1 = c_o[m][n][1] * i0;
            const float v2 = c_o[m][n][2] * i1, v3 = c_o[m][n][3] * i1;
            const __half h0 = __float2half(v0), h1 = __float2half(v1);
            const __half h2 = __float2half(v2), h3 = __float2half(v3);
            const __half e0 = __float2half(v0 - __half2float(h0));
            const __half e1 = __float2half(v1 - __half2float(h1));
            const __half e2 = __float2half(v2 - __half2float(h2));
            const __half e3 = __float2half(v3 - __half2float(h3));
            *(uint32_t*)(g_ahi + a0 + dcol) = hf2u(h0, h1);
            *(uint32_t*)(g_alo + a0 + dcol) = hf2u(e0, e1);
            *(uint32_t*)(g_ahi + a1 + dcol) = hf2u(h2, h3);
            *(uint32_t*)(g_alo + a1 + dcol) = hf2u(e2, e3);
        }
    }
}

// ---------------------------------------------------------------------------
extern "C" void kernel_launch(void* const* d_in, const int* in_sizes, int n_in,
                              void* d_out, int out_size) {
    const float* query = 0;
    const float* W_qkv = 0;
    const float* b_qkv = 0;
    const float* W_out = 0;
    const float* b_out = 0;
    for (int i = 0; i < n_in; i++) {
        switch (in_sizes[i]) {
            case 4194304: query = (const float*)d_in[i]; break;
            case 3145728: W_qkv = (const float*)d_in[i]; break;
            case 3072:    b_qkv = (const float*)d_in[i]; break;
            case 1048576: W_out = (const float*)d_in[i]; break;
            case 1024:    b_out = (const float*)d_in[i]; break;
        }
    }
    float* out = (float*)d_out;

    cudaFuncSetAttribute(mma_gemm_kernel<0>, cudaFuncAttributeMaxDynamicSharedMemorySize, GSMEM);
    cudaFuncSetAttribute(mma_gemm_kernel<1>, cudaFuncAttributeMaxDynamicSharedMemorySize, GSMEM);
    cudaFuncSetAttribute(attn_mma_kernel, cudaFuncAttributeMaxDynamicSharedMemorySize, ATTN_SMEM);

    rope_table_kernel<<<(SEQ * 32 + 255) / 256, 256>>>();
    split_x_kernel<<<NTOK * DIM / 1024, 256>>>(query);
    transpose_f16_kernel<<<dim3(QKV_N / 32, DIM / 32), dim3(32, 8)>>>(W_qkv, 0);
    transpose_f16_kernel<<<dim3(DIM / 32, DIM / 32), dim3(32, 8)>>>(W_out, 1);

    mma_gemm_kernel<0><<<dim3(QKV_N / 128, NTOK / 128), 256, GSMEM>>>(b_qkv, nullptr);

    attn_mma_kernel<<<dim3(BATCH * HEADS, SEQ / 128), 128, ATTN_SMEM>>>();

    mma_gemm_kernel<1><<<dim3(DIM / 128, NTOK / 128), 256, GSMEM>>>(b_out, out);
}